// round 12
// baseline (speedup 1.0000x reference)
#include <cuda_runtime.h>
#include <cuda_fp16.h>
#include <math.h>
#include <stdint.h>

#define DM 384
#define DI 768
#define NSTATE 16
#define NB 8
#define SEQ 1024
#define ND 4
#define DXZ 1536          // 2*DI
#define NJ 6144           // ND*DXZ
#define NR 8192           // NB*SEQ rows
#define NXD 56            // dt_rank(24) + 2*16 (logical)
#define NXDP 64           // padded x_dbl row stride
#define KCMB 3072         // ND*DI combined K for output GEMM
#define NCHUNK 8
#define CHS 128           // steps per scan chunk

// ---------------- scratch (device globals; no cudaMalloc allowed) ------------
__device__ float g_xz[(size_t)NR * NJ];           // in_proj output (natural order)
__device__ float g_uc[(size_t)ND * NR * DI];      // post conv+silu
__device__ float g_xdbl[(size_t)ND * NR * NXDP];  // [d][row][64] dt|B|C (padded)
__device__ float g_r[(size_t)NR * DM];            // pre-LN residual
__device__ float g_chkP[(size_t)ND * NB * NCHUNK * NSTATE * DI];
__device__ float g_chkH[(size_t)ND * NB * NCHUNK * NSTATE * DI];
__device__ float g_hin[(size_t)ND * NB * NCHUNK * NSTATE * DI];
__device__ float g_dlt[(size_t)ND * NR * DI];     // delta (softplus output)
__device__ float g_qv[(size_t)ND * NR * DI];      // exp(-delta)
__device__ __half g_x16[(size_t)NR * DM];         // x in fp16
__device__ __half g_win16[(size_t)NJ * DM];       // W_in in fp16
__device__ __half g_wcomb16[(size_t)DM * KCMB];   // combined out-proj weight, fp16
__device__ __half g_yg16[(size_t)NR * KCMB];      // gated scan output, fp16, ORIGINAL order

// ---------------- cross-scan permutations ------------------------------------
__device__ __forceinline__ int orig_of_scan(int d, int p) {
    int hi = p >> 5, lo = p & 31;
    if (d == 0) return p;
    if (d == 1) return hi * 32 + (31 - lo);
    if (d == 2) return lo * 32 + hi;
    return (31 - lo) * 32 + hi;
}

// ---------------- mma / cp.async helpers --------------------------------------
__device__ __forceinline__ uint32_t to_tf32(float x) {
    uint32_t r;
    asm("cvt.rna.tf32.f32 %0, %1;" : "=r"(r) : "f"(x));
    return r;
}
__device__ __forceinline__ void mma_tf32(float* c, const uint32_t* a, const uint32_t* b) {
    asm volatile(
        "mma.sync.aligned.m16n8k8.row.col.f32.tf32.tf32.f32 "
        "{%0,%1,%2,%3}, {%4,%5,%6,%7}, {%8,%9}, {%0,%1,%2,%3};"
        : "+f"(c[0]), "+f"(c[1]), "+f"(c[2]), "+f"(c[3])
        : "r"(a[0]), "r"(a[1]), "r"(a[2]), "r"(a[3]), "r"(b[0]), "r"(b[1]));
}
__device__ __forceinline__ void mma_fp16(float* c, const uint32_t* a, const uint32_t* b) {
    asm volatile(
        "mma.sync.aligned.m16n8k16.row.col.f32.f16.f16.f32 "
        "{%0,%1,%2,%3}, {%4,%5,%6,%7}, {%8,%9}, {%0,%1,%2,%3};"
        : "+f"(c[0]), "+f"(c[1]), "+f"(c[2]), "+f"(c[3])
        : "r"(a[0]), "r"(a[1]), "r"(a[2]), "r"(a[3]), "r"(b[0]), "r"(b[1]));
}
__device__ __forceinline__ void cpa16(void* sm, const void* g) {
    uint32_t sa = (uint32_t)__cvta_generic_to_shared(sm);
    asm volatile("cp.async.ca.shared.global [%0], [%1], 16;" :: "r"(sa), "l"(g));
}
#define CP_COMMIT() asm volatile("cp.async.commit_group;")
#define CP_WAIT2() asm volatile("cp.async.wait_group 2;")

// ---------------- prep: fp32 -> fp16 ------------------------------------------
__global__ __launch_bounds__(256) void k_tohalf(const float4* __restrict__ src,
                                                __half2* __restrict__ dst, int n4) {
    int i = blockIdx.x * 256 + threadIdx.x;
    if (i < n4) {
        float4 v = src[i];
        dst[2 * i] = __floats2half2_rn(v.x, v.y);
        dst[2 * i + 1] = __floats2half2_rn(v.z, v.w);
    }
}

// ---------------- K_GEMM (FP16 mma, cp.async 4-stage): C = A[MxK]*B[NxK]^T ----
// 128(M)x64(N) tile, k16/stage, 128 threads = 4 warps (2m x 2n), warp tile 64x32.
// 4 CTAs/SM -> 4 independent barrier domains (vs 2 with 256-thread CTAs).
template <int EPI>
__global__ __launch_bounds__(128, 4) void k_gemm_fp16(
    const __half* __restrict__ A, const __half* __restrict__ B,
    float* __restrict__ C, int K, int ldc,
    const float* __restrict__ X, const float* __restrict__ bias) {
    __shared__ __align__(16) uint32_t As[4][128][12];
    __shared__ __align__(16) uint32_t Bs[4][64][12];
    const int tid = threadIdx.x;
    const int m0 = blockIdx.y * 128, n0 = blockIdx.x * 64;
    const int lane = tid & 31, warp = tid >> 5;
    const int wm = warp >> 1, wn = warp & 1;
    const int g = lane >> 2, t = lane & 3;

    const __half* Ag = A + (size_t)(m0 + tid) * K;         // row tid, 2 chunks of 16B
    const __half* Bg = B + (size_t)(n0 + (tid & 63)) * K;  // tid<64 loads B
    const bool bldr = (tid < 64);

    float acc[4][4][4];
#pragma unroll
    for (int i = 0; i < 4; i++)
#pragma unroll
        for (int j = 0; j < 4; j++)
#pragma unroll
            for (int q = 0; q < 4; q++) acc[i][j][q] = 0.f;

    const int nt = K >> 4;
#pragma unroll
    for (int s = 0; s < 3; s++) {
        cpa16(&As[s][tid][0], Ag + s * 16);
        cpa16(&As[s][tid][4], Ag + s * 16 + 8);
        if (bldr) {
            cpa16(&Bs[s][tid][0], Bg + s * 16);
            cpa16(&Bs[s][tid][4], Bg + s * 16 + 8);
        }
        CP_COMMIT();
    }

    for (int tt = 0; tt < nt; tt++) {
        CP_WAIT2();
        __syncthreads();
        const int st = tt & 3;
        uint32_t afr[4][4], bfr[4][2];
#pragma unroll
        for (int i = 0; i < 4; i++) {
            const int am = wm * 64 + i * 16 + g;
            afr[i][0] = As[st][am][t];
            afr[i][1] = As[st][am + 8][t];
            afr[i][2] = As[st][am][t + 4];
            afr[i][3] = As[st][am + 8][t + 4];
        }
#pragma unroll
        for (int j = 0; j < 4; j++) {
            const int bn = wn * 32 + j * 8 + g;
            bfr[j][0] = Bs[st][bn][t];
            bfr[j][1] = Bs[st][bn][t + 4];
        }
#pragma unroll
        for (int i = 0; i < 4; i++)
#pragma unroll
            for (int j = 0; j < 4; j++) mma_fp16(acc[i][j], afr[i], bfr[j]);
        const int tn = tt + 3;
        if (tn < nt) {
            cpa16(&As[tn & 3][tid][0], Ag + tn * 16);
            cpa16(&As[tn & 3][tid][4], Ag + tn * 16 + 8);
            if (bldr) {
                cpa16(&Bs[tn & 3][tid][0], Bg + tn * 16);
                cpa16(&Bs[tn & 3][tid][4], Bg + tn * 16 + 8);
            }
        }
        CP_COMMIT();
    }

#pragma unroll
    for (int i = 0; i < 4; i++) {
        const int r0 = m0 + wm * 64 + i * 16 + g;
        const int r1 = r0 + 8;
#pragma unroll
        for (int j = 0; j < 4; j++) {
            const int cidx = n0 + wn * 32 + j * 8 + 2 * t;
            float2 s0 = make_float2(acc[i][j][0], acc[i][j][1]);
            float2 s1 = make_float2(acc[i][j][2], acc[i][j][3]);
            if (EPI == 1) {
                float2 x0 = *(const float2*)(X + (size_t)r0 * DM + cidx);
                float2 x1 = *(const float2*)(X + (size_t)r1 * DM + cidx);
                float2 bb = *(const float2*)(bias + cidx);
                s0.x += x0.x + bb.x; s0.y += x0.y + bb.y;
                s1.x += x1.x + bb.x; s1.y += x1.y + bb.y;
            }
            *(float2*)(C + (size_t)r0 * ldc + cidx) = s0;
            *(float2*)(C + (size_t)r1 * ldc + cidx) = s1;
        }
    }
}

// ---------------- K3: x_dbl (TF32 mma): per d, [8192x768]@[56x768]^T ---------
__global__ __launch_bounds__(256) void k_xdbl_tf32(const float* __restrict__ Wx) {
    __shared__ __align__(16) uint32_t As[2][16][136];
    __shared__ __align__(16) uint32_t Bs[2][16][72];
    const int tid = threadIdx.x;
    const int d = blockIdx.y;
    const int m0 = blockIdx.x * 128;
    const float* Auc = g_uc + (size_t)d * NR * DI;
    const float* Bw = Wx + (size_t)d * NXD * DI;

    const int arow = tid & 127, ak = (tid >> 7) * 8;
    const int brow = tid & 63, bk = (tid >> 6) * 4;
    const int lane = tid & 31, warp = tid >> 5;
    const int wm = warp >> 1, wn = warp & 1;
    const int g = lane >> 2, kA = lane & 3;

    const float* Ag = Auc + (size_t)(m0 + arow) * DI + ak;
    const float* Bg = Bw + (size_t)brow * DI + bk;
    const bool bvalid = (brow < NXD);

    float acc[2][4][4];
#pragma unroll
    for (int i = 0; i < 2; i++)
#pragma unroll
        for (int j = 0; j < 4; j++)
#pragma unroll
            for (int q = 0; q < 4; q++) acc[i][j][q] = 0.f;

    const int ntiles = DI >> 4;
    float4 pa0, pa1, pb0;
    pa0 = *(const float4*)(Ag);
    pa1 = *(const float4*)(Ag + 4);
    pb0 = bvalid ? *(const float4*)(Bg) : make_float4(0.f, 0.f, 0.f, 0.f);
    {
        float av[8] = {pa0.x, pa0.y, pa0.z, pa0.w, pa1.x, pa1.y, pa1.z, pa1.w};
        float bv[4] = {pb0.x, pb0.y, pb0.z, pb0.w};
#pragma unroll
        for (int q = 0; q < 8; q++) As[0][ak + q][arow] = to_tf32(av[q]);
#pragma unroll
        for (int q = 0; q < 4; q++) Bs[0][bk + q][brow] = to_tf32(bv[q]);
    }
    __syncthreads();

    for (int t = 0; t < ntiles; t++) {
        const int cur = t & 1;
        if (t + 1 < ntiles) {
            const int k0 = (t + 1) << 4;
            pa0 = *(const float4*)(Ag + k0);
            pa1 = *(const float4*)(Ag + k0 + 4);
            pb0 = bvalid ? *(const float4*)(Bg + k0) : make_float4(0.f, 0.f, 0.f, 0.f);
        }
#pragma unroll
        for (int k8 = 0; k8 < 16; k8 += 8) {
            uint32_t afr[2][4], bfr[4][2];
            const int kr0 = k8 + kA, kr1 = k8 + kA + 4;
#pragma unroll
            for (int i = 0; i < 2; i++) {
                const int am = wm * 32 + i * 16 + g;
                afr[i][0] = As[cur][kr0][am];
                afr[i][1] = As[cur][kr0][am + 8];
                afr[i][2] = As[cur][kr1][am];
                afr[i][3] = As[cur][kr1][am + 8];
            }
#pragma unroll
            for (int j = 0; j < 4; j++) {
                const int bn = wn * 32 + j * 8 + g;
                bfr[j][0] = Bs[cur][kr0][bn];
                bfr[j][1] = Bs[cur][kr1][bn];
            }
#pragma unroll
            for (int i = 0; i < 2; i++)
#pragma unroll
                for (int j = 0; j < 4; j++) mma_tf32(acc[i][j], afr[i], bfr[j]);
        }
        if (t + 1 < ntiles) {
            const int nxt = cur ^ 1;
            float av[8] = {pa0.x, pa0.y, pa0.z, pa0.w, pa1.x, pa1.y, pa1.z, pa1.w};
            float bv[4] = {pb0.x, pb0.y, pb0.z, pb0.w};
#pragma unroll
            for (int q = 0; q < 8; q++) As[nxt][ak + q][arow] = to_tf32(av[q]);
#pragma unroll
            for (int q = 0; q < 4; q++) Bs[nxt][bk + q][brow] = to_tf32(bv[q]);
            __syncthreads();
        }
    }

#pragma unroll
    for (int i = 0; i < 2; i++) {
        const int r0 = m0 + wm * 32 + i * 16 + g;
        const int r1 = r0 + 8;
#pragma unroll
        for (int j = 0; j < 4; j++) {
            const int cidx = wn * 32 + j * 8 + 2 * kA;
            *(float2*)(g_xdbl + ((size_t)d * NR + r0) * NXDP + cidx) =
                make_float2(acc[i][j][0], acc[i][j][1]);
            *(float2*)(g_xdbl + ((size_t)d * NR + r1) * NXDP + cidx) =
                make_float2(acc[i][j][2], acc[i][j][3]);
        }
    }
}

// ---------------- K0: W_comb (fp16 output) ------------------------------------
__global__ __launch_bounds__(256) void k_wcomb(const float* __restrict__ Wproj,
                                               const float* __restrict__ Wout) {
    __shared__ float As[16 * 68];
    __shared__ float Bs[16 * 68];
    const int d = blockIdx.z;
    const int j0 = blockIdx.y * 64, c0 = blockIdx.x * 64;
    const int tid = threadIdx.x;
    const int tx = tid & 15, ty = tid >> 4;
    const int lm = tid >> 2, lk = (tid & 3) * 4;
    float acc[4][4];
#pragma unroll
    for (int i = 0; i < 4; i++)
#pragma unroll
        for (int j = 0; j < 4; j++) acc[i][j] = 0.f;

    for (int k0 = 0; k0 < DM; k0 += 16) {
        float4 av = *(const float4*)(Wproj + (size_t)(j0 + lm) * (4 * DM) + d * DM + k0 + lk);
        As[(lk + 0) * 68 + lm] = av.x;
        As[(lk + 1) * 68 + lm] = av.y;
        As[(lk + 2) * 68 + lm] = av.z;
        As[(lk + 3) * 68 + lm] = av.w;
#pragma unroll
        for (int pass = 0; pass < 4; pass++) {
            int idx = tid + pass * 256;
            int kk = idx >> 6, cc = idx & 63;
            Bs[kk * 68 + cc] = Wout[((size_t)d * DM + k0 + kk) * DI + c0 + cc];
        }
        __syncthreads();
#pragma unroll
        for (int kk = 0; kk < 16; kk++) {
            float4 a = *(const float4*)(As + kk * 68 + ty * 4);
            float4 b = *(const float4*)(Bs + kk * 68 + tx * 4);
            float am[4] = {a.x, a.y, a.z, a.w};
            float bm[4] = {b.x, b.y, b.z, b.w};
#pragma unroll
            for (int i = 0; i < 4; i++)
#pragma unroll
                for (int j = 0; j < 4; j++) acc[i][j] += am[i] * bm[j];
        }
        __syncthreads();
    }
#pragma unroll
    for (int i = 0; i < 4; i++) {
        __half2* dst = (__half2*)(g_wcomb16 + (size_t)(j0 + ty * 4 + i) * KCMB + d * DI + c0 + tx * 4);
        dst[0] = __floats2half2_rn(acc[i][0], acc[i][1]);
        dst[1] = __floats2half2_rn(acc[i][2], acc[i][3]);
    }
}

// ---------------- K2: depthwise causal conv (run-length 16) + SiLU -----------
__global__ __launch_bounds__(128) void k_conv2(const float* __restrict__ convw,
                                               const float* __restrict__ convb) {
    const int tid = threadIdx.x;
    const int c = blockIdx.x * 128 + tid;
    const int seg = blockIdx.y;
    const int bz = blockIdx.z;
    const int d = bz >> 3, b = bz & 7;
    const int p0 = seg * 16;

    float4 w4 = *(const float4*)(convw + ((size_t)d * DI + c) * 4);
    const float bias = convb[d * DI + c];
    const float* xzbase = g_xz + (size_t)b * SEQ * NJ + d * DXZ + c;

    float v[19];
#pragma unroll
    for (int j = 0; j < 19; j++) {
        int q = p0 + j - 3;
        v[j] = (q >= 0) ? xzbase[(size_t)orig_of_scan(d, q) * NJ] : 0.f;
    }
    float* ucp = g_uc + ((size_t)(d * 8 + b) * SEQ + p0) * DI + c;
#pragma unroll
    for (int k = 0; k < 16; k++) {
        float acc = bias + w4.x * v[k] + w4.y * v[k + 1] + w4.z * v[k + 2] + w4.w * v[k + 3];
        ucp[(size_t)k * DI] = __fdividef(acc, 1.f + __expf(-acc));
    }
}

// ---------------- K4a: scan pass1 — delta/qv store + chunk summaries ---------
__global__ __launch_bounds__(128) void k_scanP(const float* __restrict__ Alog,
                                               const float* __restrict__ Wdt,
                                               const float* __restrict__ bdt) {
    __shared__ __align__(16) float xs[2][8][NXDP];
    const int d = blockIdx.z;
    const int b = blockIdx.y >> 3, j = blockIdx.y & 7;
    const int tid = threadIdx.x;
    const int c = blockIdx.x * 128 + tid;
    const bool full = (j < 7);

    float w[24];
    {
        const float* wr = Wdt + ((size_t)d * DI + c) * 24;
#pragma unroll
        for (int q = 0; q < 6; q++) {
            float4 vv = *(const float4*)(wr + q * 4);
            w[q * 4] = vv.x; w[q * 4 + 1] = vv.y; w[q * 4 + 2] = vv.z; w[q * 4 + 3] = vv.w;
        }
    }
    const float bb = bdt[d * DI + c];
    float a[NSTATE];
#pragma unroll
    for (int n = 0; n < NSTATE; n++) a[n] = -__expf(Alog[((size_t)d * DI + c) * NSTATE + n]);
    bool structured = true;
#pragma unroll
    for (int n = 1; n < NSTATE; n++) {
        float e = (float)(n + 1) * a[0];
        if (fabsf(a[n] - e) > 1e-4f * fabsf(e) + 1e-12f) structured = false;
    }

    const int p0 = j * CHS;
    const size_t rbase = (size_t)d * NR + (size_t)b * SEQ + p0;
    const float* uptr = g_uc + rbase * DI + c;
    const float* xrowbase = g_xdbl + rbase * NXDP;
    float* dptr = g_dlt + rbase * DI + c;
    float* qptr = g_qv + rbase * DI + c;
    const int srow = tid >> 4, scol = (tid & 15) * 4;

    *(float4*)&xs[0][srow][scol] = *(const float4*)(xrowbase + (size_t)srow * NXDP + scol);
    float ucur[8], unxt[8];
#pragma unroll
    for (int k = 0; k < 8; k++) ucur[k] = uptr[(size_t)k * DI];
    __syncthreads();

    float h[NSTATE];
#pragma unroll
    for (int n = 0; n < NSTATE; n++) h[n] = 0.f;
    float S = 0.f;

    const int NCH = CHS / 8;
    for (int ch = 0; ch < NCH; ch++) {
        const int buf = ch & 1;
        const int pn = (ch + 1 < NCH) ? (ch + 1) * 8 : ch * 8;
        *(float4*)&xs[buf ^ 1][srow][scol] =
            *(const float4*)(xrowbase + (size_t)(pn + srow) * NXDP + scol);
#pragma unroll
        for (int k = 0; k < 8; k++) unxt[k] = uptr[(size_t)(pn + k) * DI];
        const int pl = ch * 8;
#pragma unroll
        for (int k = 0; k < 8; k++) {
            const float* row = &xs[buf][k][0];
            float s = bb;
#pragma unroll
            for (int q = 0; q < 6; q++) {
                float4 vv = *(const float4*)(row + q * 4);
                s += vv.x * w[q * 4] + vv.y * w[q * 4 + 1] + vv.z * w[q * 4 + 2] + vv.w * w[q * 4 + 3];
            }
            float es = __expf(s);
            float qv = __fdividef(1.f, 1.f + es);
            float delta = (s > 80.f) ? s : __logf(1.f + es);
            dptr[(size_t)(pl + k) * DI] = delta;
            qptr[(size_t)(pl + k) * DI] = qv;
            if (full) {
                float dA[16];
                if (structured) {
                    float q2 = qv * qv, q4 = q2 * q2, q8 = q4 * q4;
                    dA[0] = qv;       dA[1] = q2;       dA[2] = q2 * qv;     dA[3] = q4;
                    dA[4] = q4 * qv;  dA[5] = q4 * q2;  dA[6] = q4 * dA[2];  dA[7] = q8;
                    dA[8] = q8 * qv;  dA[9] = q8 * q2;  dA[10] = q8 * dA[2]; dA[11] = q8 * q4;
                    dA[12] = q8 * dA[4]; dA[13] = q8 * dA[5]; dA[14] = q8 * dA[6]; dA[15] = q8 * q8;
                } else {
#pragma unroll
                    for (int n = 0; n < 16; n++) dA[n] = __expf(delta * a[n]);
                }
                float4 B0 = *(const float4*)(row + 24);
                float4 B1 = *(const float4*)(row + 28);
                float4 B2 = *(const float4*)(row + 32);
                float4 B3 = *(const float4*)(row + 36);
                float Bv[16] = {B0.x, B0.y, B0.z, B0.w, B1.x, B1.y, B1.z, B1.w,
                                B2.x, B2.y, B2.z, B2.w, B3.x, B3.y, B3.z, B3.w};
                const float du = delta * ucur[k];
                S += delta;
#pragma unroll
                for (int n = 0; n < 16; n++) h[n] = dA[n] * h[n] + du * Bv[n];
            }
        }
#pragma unroll
        for (int k = 0; k < 8; k++) ucur[k] = unxt[k];
        __syncthreads();
    }

    if (full) {
        float P[16];
        if (structured) {
            float qS = __expf(a[0] * S);
            float q2 = qS * qS, q4 = q2 * q2, q8 = q4 * q4;
            P[0] = qS;       P[1] = q2;       P[2] = q2 * qS;    P[3] = q4;
            P[4] = q4 * qS;  P[5] = q4 * q2;  P[6] = q4 * P[2];  P[7] = q8;
            P[8] = q8 * qS;  P[9] = q8 * q2;  P[10] = q8 * P[2]; P[11] = q8 * q4;
            P[12] = q8 * P[4]; P[13] = q8 * P[5]; P[14] = q8 * P[6]; P[15] = q8 * q8;
        } else {
#pragma unroll
            for (int n = 0; n < 16; n++) P[n] = __expf(a[n] * S);
        }
        const size_t obase = (((size_t)(d * 8 + b) * NCHUNK + j) * NSTATE) * DI + c;
#pragma unroll
        for (int n = 0; n < 16; n++) {
            g_chkP[obase + (size_t)n * DI] = P[n];
            g_chkH[obase + (size_t)n * DI] = h[n];
        }
    }
}

// ---------------- K4b: combine chunk states ----------------------------------
__global__ __launch_bounds__(256) void k_comb() {
    const int c = blockIdx.x * 256 + threadIdx.x;
    const int b = blockIdx.y, d = blockIdx.z;
    float h[NSTATE];
#pragma unroll
    for (int n = 0; n < NSTATE; n++) h[n] = 0.f;
    const size_t base = ((size_t)(d * 8 + b) * NCHUNK) * NSTATE * DI + c;
    for (int j = 0; j < NCHUNK; j++) {
        const size_t jb = base + (size_t)j * NSTATE * DI;
#pragma unroll
        for (int n = 0; n < NSTATE; n++) g_hin[jb + (size_t)n * DI] = h[n];
        if (j < NCHUNK - 1) {
#pragma unroll
            for (int n = 0; n < NSTATE; n++)
                h[n] = g_chkP[jb + (size_t)n * DI] * h[n] + g_chkH[jb + (size_t)n * DI];
        }
    }
}

// ---------------- K4c: scan pass2 — recurrence + output (fp16 yg store) ------
__global__ __launch_bounds__(128) void k_scan2(const float* __restrict__ Alog,
                                               const float* __restrict__ Dpar) {
    __shared__ __align__(16) float xs[2][8][32];   // B|C only
    const int d = blockIdx.z;
    const int b = blockIdx.y >> 3, j = blockIdx.y & 7;
    const int tid = threadIdx.x;
    const int c = blockIdx.x * 128 + tid;

    const float Dp = Dpar[d * DI + c];
    const size_t abase = ((size_t)d * DI + c) * NSTATE;
    float a0 = -__expf(Alog[abase]);
    bool structured = true;
#pragma unroll
    for (int n = 1; n < NSTATE; n++) {
        float an = -__expf(Alog[abase + n]);
        float e = (float)(n + 1) * a0;
        if (fabsf(an - e) > 1e-4f * fabsf(e) + 1e-12f) structured = false;
    }

    const int p0 = j * CHS;
    const size_t rbase = (size_t)d * NR + (size_t)b * SEQ + p0;
    const float* uptr = g_uc + rbase * DI + c;
    const float* dptr = g_dlt + rbase * DI + c;
    const float* qptr = g_qv + rbase * DI + c;
    const float* zbase = g_xz + (size_t)b * SEQ * NJ + d * DXZ + DI + c;
    __half* ybase = g_yg16 + (size_t)b * SEQ * KCMB + (size_t)d * DI + c;
    const float* xrowbase = g_xdbl + rbase * NXDP + 24;

    float h[NSTATE];
    {
        const size_t hbase = (((size_t)(d * 8 + b) * NCHUNK + j) * NSTATE) * DI + c;
#pragma unroll
        for (int n = 0; n < NSTATE; n++) h[n] = g_hin[hbase + (size_t)n * DI];
    }

    const int srow = tid >> 3, scol = (tid & 7) * 4;
    if (tid < 64)
        *(float4*)&xs[0][srow][scol] = *(const float4*)(xrowbase + (size_t)srow * NXDP + scol);
    float ucur[8], zcur[8], dcur[8], qcur[8];
    float unxt[8], znxt[8], dnxt[8], qnxt[8];
#pragma unroll
    for (int k = 0; k < 8; k++) {
        ucur[k] = uptr[(size_t)k * DI];
        dcur[k] = dptr[(size_t)k * DI];
        qcur[k] = qptr[(size_t)k * DI];
        zcur[k] = zbase[(size_t)orig_of_scan(d, p0 + k) * NJ];
    }
    __syncthreads();

    const int NCH = CHS / 8;
    for (int ch = 0; ch < NCH; ch++) {
        const int buf = ch & 1;
        const int pn = (ch + 1 < NCH) ? (ch + 1) * 8 : ch * 8;
        if (tid < 64)
            *(float4*)&xs[buf ^ 1][srow][scol] =
                *(const float4*)(xrowbase + (size_t)(pn + srow) * NXDP + scol);
#pragma unroll
        for (int k = 0; k < 8; k++) {
            unxt[k] = uptr[(size_t)(pn + k) * DI];
            dnxt[k] = dptr[(size_t)(pn + k) * DI];
            qnxt[k] = qptr[(size_t)(pn + k) * DI];
            znxt[k] = zbase[(size_t)orig_of_scan(d, p0 + pn + k) * NJ];
        }
        const int pl = ch * 8;
#pragma unroll
        for (int k = 0; k < 8; k++) {
            const float* row = &xs[buf][k][0];
            const float delta = dcur[k];
            const float qv = qcur[k];
            float dA[16];
            if (structured) {
                float q2 = qv * qv, q4 = q2 * q2, q8 = q4 * q4;
                dA[0] = qv;       dA[1] = q2;       dA[2] = q2 * qv;     dA[3] = q4;
                dA[4] = q4 * qv;  dA[5] = q4 * q2;  dA[6] = q4 * dA[2];  dA[7] = q8;
                dA[8] = q8 * qv;  dA[9] = q8 * q2;  dA[10] = q8 * dA[2]; dA[11] = q8 * q4;
                dA[12] = q8 * dA[4]; dA[13] = q8 * dA[5]; dA[14] = q8 * dA[6]; dA[15] = q8 * q8;
            } else {
#pragma unroll
                for (int n = 0; n < 16; n++)
                    dA[n] = __expf(delta * (-__expf(Alog[abase + n])));
            }
            float4 B0 = *(const float4*)(row + 0);
            float4 B1 = *(const float4*)(row + 4);
            float4 B2 = *(const float4*)(row + 8);
            float4 B3 = *(const float4*)(row + 12);
            float4 C0 = *(const float4*)(row + 16);
            float4 C1 = *(const float4*)(row + 20);
            float4 C2 = *(const float4*)(row + 24);
            float4 C3 = *(const float4*)(row + 28);
            float Bv[16] = {B0.x, B0.y, B0.z, B0.w, B1.x, B1.y, B1.z, B1.w,
                            B2.x, B2.y, B2.z, B2.w, B3.x, B3.y, B3.z, B3.w};
            float Cv[16] = {C0.x, C0.y, C0.z, C0.w, C1.x, C1.y, C1.z, C1.w,
                            C2.x, C2.y, C2.z, C2.w, C3.x, C3.y, C3.z, C3.w};
            const float u = ucur[k];
            const float du = delta * u;
            float acc0 = 0.f, acc1 = 0.f, acc2 = 0.f, acc3 = 0.f;
#pragma unroll
            for (int n = 0; n < 16; n += 4) {
                h[n] = dA[n] * h[n] + du * Bv[n];                 acc0 += h[n] * Cv[n];
                h[n + 1] = dA[n + 1] * h[n + 1] + du * Bv[n + 1]; acc1 += h[n + 1] * Cv[n + 1];
                h[n + 2] = dA[n + 2] * h[n + 2] + du * Bv[n + 2]; acc2 += h[n + 2] * Cv[n + 2];
                h[n + 3] = dA[n + 3] * h[n + 3] + du * Bv[n + 3]; acc3 += h[n + 3] * Cv[n + 3];
            }
            float y = (acc0 + acc1) + (acc2 + acc3) + u * Dp;
            float z = zcur[k];
            float sg = __fdividef(z, 1.f + __expf(-z));
            ybase[(size_t)orig_of_scan(d, p0 + pl + k) * KCMB] = __float2half_rn(y * sg);
        }
#pragma unroll
        for (int k = 0; k < 8; k++) {
            ucur[k] = unxt[k]; zcur[k] = znxt[k];
            dcur[k] = dnxt[k]; qcur[k] = qnxt[k];
        }
        __syncthreads();
    }
}

// ---------------- K6: LayerNorm ----------------------------------------------
__global__ __launch_bounds__(128) void k_ln(const float* __restrict__ gam,
                                            const float* __restrict__ bet,
                                            float* __restrict__ out) {
    const int r = blockIdx.x;
    const int tid = threadIdx.x;
    __shared__ float s1[4], s2[4];
    const float* row = g_r + (size_t)r * DM;
    float v0 = row[tid], v1 = row[tid + 128], v2 = row[tid + 256];
    float a = v0 + v1 + v2;
    float b = v0 * v0 + v1 * v1 + v2 * v2;
#pragma unroll
    for (int off = 16; off; off >>= 1) {
        a += __shfl_down_sync(0xffffffffu, a, off);
        b += __shfl_down_sync(0xffffffffu, b, off);
    }
    if ((tid & 31) == 0) { s1[tid >> 5] = a; s2[tid >> 5] = b; }
    __syncthreads();
    float ssum = s1[0] + s1[1] + s1[2] + s1[3];
    float ssq = s2[0] + s2[1] + s2[2] + s2[3];
    float mu = ssum * (1.f / 384.f);
    float var = ssq * (1.f / 384.f) - mu * mu;
    float rstd = rsqrtf(var + 1e-5f);
    out[(size_t)r * DM + tid] = gam[tid] * (v0 - mu) * rstd + bet[tid];
    out[(size_t)r * DM + tid + 128] = gam[tid + 128] * (v1 - mu) * rstd + bet[tid + 128];
    out[(size_t)r * DM + tid + 256] = gam[tid + 256] * (v2 - mu) * rstd + bet[tid + 256];
}

// ---------------- launch ------------------------------------------------------
extern "C" void kernel_launch(void* const* d_in, const int* in_sizes, int n_in,
                              void* d_out, int out_size) {
    const float* x = (const float*)d_in[0];
    const float* Win = (const float*)d_in[1];
    const float* convw = (const float*)d_in[2];
    const float* convb = (const float*)d_in[3];
    const float* Wx = (const float*)d_in[4];
    const float* Wdt = (const float*)d_in[5];
    const float* bdt = (const float*)d_in[6];
    const float* Alog = (const float*)d_in[7];
    const float* Dpar = (const float*)d_in[8];
    const float* Wout = (const float*)d_in[9];
    const float* Wproj = (const float*)d_in[10];
    const float* bproj = (const float*)d_in[11];
    const float* lng = (const float*)d_in[12];
    const float* lnb = (const float*)d_in[13];
    float* out = (float*)d_out;

    static float* p_xz = nullptr;
    static float* p_r = nullptr;
    static __half* p_x16 = nullptr;
    static __half* p_win16 = nullptr;
    static __half* p_wc16 = nullptr;
    static __half* p_yg16 = nullptr;
    if (!p_xz) {
        cudaGetSymbolAddress((void**)&p_xz, g_xz);
        cudaGetSymbolAddress((void**)&p_r, g_r);
        cudaGetSymbolAddress((void**)&p_x16, g_x16);
        cudaGetSymbolAddress((void**)&p_win16, g_win16);
        cudaGetSymbolAddress((void**)&p_wc16, g_wcomb16);
        cudaGetSymbolAddress((void**)&p_yg16, g_yg16);
    }

    const int nx4 = NR * DM / 4;
    const int nw4 = NJ * DM / 4;
    k_tohalf<<<(nx4 + 255) / 256, 256>>>((const float4*)x, (__half2*)p_x16, nx4);
    k_tohalf<<<(nw4 + 255) / 256, 256>>>((const float4*)Win, (__half2*)p_win16, nw4);
    k_wcomb<<<dim3(DI / 64, DM / 64, ND), 256>>>(Wproj, Wout);
    k_gemm_fp16<0><<<dim3(NJ / 64, NR / 128), 128>>>(p_x16, p_win16, p_xz, DM, NJ, nullptr, nullptr);
    k_conv2<<<dim3(DI / 128, SEQ / 16, ND * NB), 128>>>(convw, convb);
    k_xdbl_tf32<<<dim3(NR / 128, ND), 256>>>(Wx);
    k_scanP<<<dim3(DI / 128, NB * 8, ND), 128>>>(Alog, Wdt, bdt);
    k_comb<<<dim3(DI / 256, NB, ND), 256>>>();
    k_scan2<<<dim3(DI / 128, NB * 8, ND), 128>>>(Alog, Dpar);
    k_gemm_fp16<1><<<dim3(DM / 64, NR / 128), 128>>>(p_yg16, p_wc16, p_r, KCMB, DM, x, bproj);
    k_ln<<<NR, 128>>>(lng, lnb, out);
}

// round 15
// speedup vs baseline: 1.1727x; 1.1727x over previous
#include <cuda_runtime.h>
#include <cuda_fp16.h>
#include <math.h>
#include <stdint.h>

#define DM 384
#define DI 768
#define NSTATE 16
#define NB 8
#define SEQ 1024
#define ND 4
#define DXZ 1536          // 2*DI
#define NJ 6144           // ND*DXZ
#define NR 8192           // NB*SEQ rows
#define NXD 56            // dt_rank(24) + 2*16 (logical)
#define NXDP 64           // padded x_dbl row stride
#define KCMB 3072         // ND*DI combined K for output GEMM
#define NCHUNK 8
#define CHS 128           // steps per scan chunk

// ---------------- scratch (device globals; no cudaMalloc allowed) ------------
__device__ float g_xz[(size_t)NR * NJ];           // in_proj output (natural order)
__device__ float g_uc[(size_t)ND * NR * DI];      // post conv+silu
__device__ float g_xdbl[(size_t)ND * NR * NXDP];  // [d][row][64] dt|B|C (padded)
__device__ float g_r[(size_t)NR * DM];            // pre-LN residual
__device__ float g_chkP[(size_t)ND * NB * NCHUNK * NSTATE * DI];
__device__ float g_chkH[(size_t)ND * NB * NCHUNK * NSTATE * DI];
__device__ float g_hin[(size_t)ND * NB * NCHUNK * NSTATE * DI];
__device__ float2 g_dq[(size_t)ND * NR * DI];     // packed {delta, exp(-delta)}
__device__ __half g_x16[(size_t)NR * DM];         // x in fp16
__device__ __half g_win16[(size_t)NJ * DM];       // W_in in fp16
__device__ __half g_wcomb16[(size_t)DM * KCMB];   // combined out-proj weight, fp16
__device__ __half g_yg16[(size_t)NR * KCMB];      // gated scan output, fp16, ORIGINAL order

// ---------------- cross-scan permutations ------------------------------------
__device__ __forceinline__ int orig_of_scan(int d, int p) {
    int hi = p >> 5, lo = p & 31;
    if (d == 0) return p;
    if (d == 1) return hi * 32 + (31 - lo);
    if (d == 2) return lo * 32 + hi;
    return (31 - lo) * 32 + hi;
}

// ---------------- mma / cp.async helpers --------------------------------------
__device__ __forceinline__ uint32_t to_tf32(float x) {
    uint32_t r;
    asm("cvt.rna.tf32.f32 %0, %1;" : "=r"(r) : "f"(x));
    return r;
}
__device__ __forceinline__ void mma_tf32(float* c, const uint32_t* a, const uint32_t* b) {
    asm volatile(
        "mma.sync.aligned.m16n8k8.row.col.f32.tf32.tf32.f32 "
        "{%0,%1,%2,%3}, {%4,%5,%6,%7}, {%8,%9}, {%0,%1,%2,%3};"
        : "+f"(c[0]), "+f"(c[1]), "+f"(c[2]), "+f"(c[3])
        : "r"(a[0]), "r"(a[1]), "r"(a[2]), "r"(a[3]), "r"(b[0]), "r"(b[1]));
}
__device__ __forceinline__ void mma_fp16(float* c, const uint32_t* a, const uint32_t* b) {
    asm volatile(
        "mma.sync.aligned.m16n8k16.row.col.f32.f16.f16.f32 "
        "{%0,%1,%2,%3}, {%4,%5,%6,%7}, {%8,%9}, {%0,%1,%2,%3};"
        : "+f"(c[0]), "+f"(c[1]), "+f"(c[2]), "+f"(c[3])
        : "r"(a[0]), "r"(a[1]), "r"(a[2]), "r"(a[3]), "r"(b[0]), "r"(b[1]));
}
__device__ __forceinline__ void cpa16cg(void* sm, const void* g) {
    uint32_t sa = (uint32_t)__cvta_generic_to_shared(sm);
    asm volatile("cp.async.cg.shared.global [%0], [%1], 16;" :: "r"(sa), "l"(g));
}
#define CP_COMMIT() asm volatile("cp.async.commit_group;")
#define CP_WAIT2() asm volatile("cp.async.wait_group 2;")

// ---------------- prep: fp32 -> fp16 ------------------------------------------
__global__ __launch_bounds__(256) void k_tohalf(const float4* __restrict__ src,
                                                __half2* __restrict__ dst, int n4) {
    int i = blockIdx.x * 256 + threadIdx.x;
    if (i < n4) {
        float4 v = src[i];
        dst[2 * i] = __floats2half2_rn(v.x, v.y);
        dst[2 * i + 1] = __floats2half2_rn(v.z, v.w);
    }
}

// ---------------- K_GEMM big (FP16 mma, 256 thr, 128x128): inproj ------------
__global__ __launch_bounds__(256, 2) void k_gemm_big(
    const __half* __restrict__ A, const __half* __restrict__ B,
    float* __restrict__ C, int K, int ldc) {
    __shared__ __align__(16) uint32_t As[4][128][12];
    __shared__ __align__(16) uint32_t Bs[4][128][12];
    const int tid = threadIdx.x;
    const int m0 = blockIdx.y * 128, n0 = blockIdx.x * 128;
    const int arow = tid & 127, au = (tid >> 7) * 4;
    const int lane = tid & 31, warp = tid >> 5;
    const int wm = warp >> 2, wn = warp & 3;
    const int g = lane >> 2, t = lane & 3;

    const __half* Ag = A + (size_t)(m0 + arow) * K + au * 2;
    const __half* Bg = B + (size_t)(n0 + arow) * K + au * 2;

    float acc[4][4][4];
#pragma unroll
    for (int i = 0; i < 4; i++)
#pragma unroll
        for (int j = 0; j < 4; j++)
#pragma unroll
            for (int q = 0; q < 4; q++) acc[i][j][q] = 0.f;

    const int nt = K >> 4;
#pragma unroll
    for (int s = 0; s < 3; s++) {
        cpa16cg(&As[s][arow][au], Ag + s * 16);
        cpa16cg(&Bs[s][arow][au], Bg + s * 16);
        CP_COMMIT();
    }

    for (int tt = 0; tt < nt; tt++) {
        CP_WAIT2();
        __syncthreads();
        const int st = tt & 3;
        uint32_t afr[4][4], bfr[4][2];
#pragma unroll
        for (int i = 0; i < 4; i++) {
            const int am = wm * 64 + i * 16 + g;
            afr[i][0] = As[st][am][t];
            afr[i][1] = As[st][am + 8][t];
            afr[i][2] = As[st][am][t + 4];
            afr[i][3] = As[st][am + 8][t + 4];
        }
#pragma unroll
        for (int j = 0; j < 4; j++) {
            const int bn = wn * 32 + j * 8 + g;
            bfr[j][0] = Bs[st][bn][t];
            bfr[j][1] = Bs[st][bn][t + 4];
        }
#pragma unroll
        for (int i = 0; i < 4; i++)
#pragma unroll
            for (int j = 0; j < 4; j++) mma_fp16(acc[i][j], afr[i], bfr[j]);
        const int tn = tt + 3;
        if (tn < nt) {
            cpa16cg(&As[tn & 3][arow][au], Ag + tn * 16);
            cpa16cg(&Bs[tn & 3][arow][au], Bg + tn * 16);
        }
        CP_COMMIT();
    }

#pragma unroll
    for (int i = 0; i < 4; i++) {
        const int r0 = m0 + wm * 64 + i * 16 + g;
        const int r1 = r0 + 8;
#pragma unroll
        for (int j = 0; j < 4; j++) {
            const int cidx = n0 + wn * 32 + j * 8 + 2 * t;
            *(float2*)(C + (size_t)r0 * ldc + cidx) = make_float2(acc[i][j][0], acc[i][j][1]);
            *(float2*)(C + (size_t)r1 * ldc + cidx) = make_float2(acc[i][j][2], acc[i][j][3]);
        }
    }
}

// ---------------- K_GEMM small (FP16 mma, 128 thr, 128x64): outproj ----------
__global__ __launch_bounds__(128, 4) void k_gemm_small(
    const __half* __restrict__ A, const __half* __restrict__ B,
    float* __restrict__ C, int K, int ldc,
    const float* __restrict__ X, const float* __restrict__ bias) {
    __shared__ __align__(16) uint32_t As[4][128][12];
    __shared__ __align__(16) uint32_t Bs[4][64][12];
    const int tid = threadIdx.x;
    const int m0 = blockIdx.y * 128, n0 = blockIdx.x * 64;
    const int lane = tid & 31, warp = tid >> 5;
    const int wm = warp >> 1, wn = warp & 1;
    const int g = lane >> 2, t = lane & 3;

    const __half* Ag = A + (size_t)(m0 + tid) * K;
    const __half* Bg = B + (size_t)(n0 + (tid & 63)) * K;
    const bool bldr = (tid < 64);

    float acc[4][4][4];
#pragma unroll
    for (int i = 0; i < 4; i++)
#pragma unroll
        for (int j = 0; j < 4; j++)
#pragma unroll
            for (int q = 0; q < 4; q++) acc[i][j][q] = 0.f;

    const int nt = K >> 4;
#pragma unroll
    for (int s = 0; s < 3; s++) {
        cpa16cg(&As[s][tid][0], Ag + s * 16);
        cpa16cg(&As[s][tid][4], Ag + s * 16 + 8);
        if (bldr) {
            cpa16cg(&Bs[s][tid][0], Bg + s * 16);
            cpa16cg(&Bs[s][tid][4], Bg + s * 16 + 8);
        }
        CP_COMMIT();
    }

    for (int tt = 0; tt < nt; tt++) {
        CP_WAIT2();
        __syncthreads();
        const int st = tt & 3;
        uint32_t afr[4][4], bfr[4][2];
#pragma unroll
        for (int i = 0; i < 4; i++) {
            const int am = wm * 64 + i * 16 + g;
            afr[i][0] = As[st][am][t];
            afr[i][1] = As[st][am + 8][t];
            afr[i][2] = As[st][am][t + 4];
            afr[i][3] = As[st][am + 8][t + 4];
        }
#pragma unroll
        for (int j = 0; j < 4; j++) {
            const int bn = wn * 32 + j * 8 + g;
            bfr[j][0] = Bs[st][bn][t];
            bfr[j][1] = Bs[st][bn][t + 4];
        }
#pragma unroll
        for (int i = 0; i < 4; i++)
#pragma unroll
            for (int j = 0; j < 4; j++) mma_fp16(acc[i][j], afr[i], bfr[j]);
        const int tn = tt + 3;
        if (tn < nt) {
            cpa16cg(&As[tn & 3][tid][0], Ag + tn * 16);
            cpa16cg(&As[tn & 3][tid][4], Ag + tn * 16 + 8);
            if (bldr) {
                cpa16cg(&Bs[tn & 3][tid][0], Bg + tn * 16);
                cpa16cg(&Bs[tn & 3][tid][4], Bg + tn * 16 + 8);
            }
        }
        CP_COMMIT();
    }

#pragma unroll
    for (int i = 0; i < 4; i++) {
        const int r0 = m0 + wm * 64 + i * 16 + g;
        const int r1 = r0 + 8;
#pragma unroll
        for (int j = 0; j < 4; j++) {
            const int cidx = n0 + wn * 32 + j * 8 + 2 * t;
            float2 s0 = make_float2(acc[i][j][0], acc[i][j][1]);
            float2 s1 = make_float2(acc[i][j][2], acc[i][j][3]);
            float2 x0 = *(const float2*)(X + (size_t)r0 * DM + cidx);
            float2 x1 = *(const float2*)(X + (size_t)r1 * DM + cidx);
            float2 bb = *(const float2*)(bias + cidx);
            s0.x += x0.x + bb.x; s0.y += x0.y + bb.y;
            s1.x += x1.x + bb.x; s1.y += x1.y + bb.y;
            *(float2*)(C + (size_t)r0 * ldc + cidx) = s0;
            *(float2*)(C + (size_t)r1 * ldc + cidx) = s1;
        }
    }
}

// ---------------- K3: x_dbl (TF32 mma): per d, [8192x768]@[56x768]^T ---------
__global__ __launch_bounds__(256) void k_xdbl_tf32(const float* __restrict__ Wx) {
    __shared__ __align__(16) uint32_t As[2][16][136];
    __shared__ __align__(16) uint32_t Bs[2][16][72];
    const int tid = threadIdx.x;
    const int d = blockIdx.y;
    const int m0 = blockIdx.x * 128;
    const float* Auc = g_uc + (size_t)d * NR * DI;
    const float* Bw = Wx + (size_t)d * NXD * DI;

    const int arow = tid & 127, ak = (tid >> 7) * 8;
    const int brow = tid & 63, bk = (tid >> 6) * 4;
    const int lane = tid & 31, warp = tid >> 5;
    const int wm = warp >> 1, wn = warp & 1;
    const int g = lane >> 2, kA = lane & 3;

    const float* Ag = Auc + (size_t)(m0 + arow) * DI + ak;
    const float* Bg = Bw + (size_t)brow * DI + bk;
    const bool bvalid = (brow < NXD);

    float acc[2][4][4];
#pragma unroll
    for (int i = 0; i < 2; i++)
#pragma unroll
        for (int j = 0; j < 4; j++)
#pragma unroll
            for (int q = 0; q < 4; q++) acc[i][j][q] = 0.f;

    const int ntiles = DI >> 4;
    float4 pa0, pa1, pb0;
    pa0 = *(const float4*)(Ag);
    pa1 = *(const float4*)(Ag + 4);
    pb0 = bvalid ? *(const float4*)(Bg) : make_float4(0.f, 0.f, 0.f, 0.f);
    {
        float av[8] = {pa0.x, pa0.y, pa0.z, pa0.w, pa1.x, pa1.y, pa1.z, pa1.w};
        float bv[4] = {pb0.x, pb0.y, pb0.z, pb0.w};
#pragma unroll
        for (int q = 0; q < 8; q++) As[0][ak + q][arow] = to_tf32(av[q]);
#pragma unroll
        for (int q = 0; q < 4; q++) Bs[0][bk + q][brow] = to_tf32(bv[q]);
    }
    __syncthreads();

    for (int t = 0; t < ntiles; t++) {
        const int cur = t & 1;
        if (t + 1 < ntiles) {
            const int k0 = (t + 1) << 4;
            pa0 = *(const float4*)(Ag + k0);
            pa1 = *(const float4*)(Ag + k0 + 4);
            pb0 = bvalid ? *(const float4*)(Bg + k0) : make_float4(0.f, 0.f, 0.f, 0.f);
        }
#pragma unroll
        for (int k8 = 0; k8 < 16; k8 += 8) {
            uint32_t afr[2][4], bfr[4][2];
            const int kr0 = k8 + kA, kr1 = k8 + kA + 4;
#pragma unroll
            for (int i = 0; i < 2; i++) {
                const int am = wm * 32 + i * 16 + g;
                afr[i][0] = As[cur][kr0][am];
                afr[i][1] = As[cur][kr0][am + 8];
                afr[i][2] = As[cur][kr1][am];
                afr[i][3] = As[cur][kr1][am + 8];
            }
#pragma unroll
            for (int j = 0; j < 4; j++) {
                const int bn = wn * 32 + j * 8 + g;
                bfr[j][0] = Bs[cur][kr0][bn];
                bfr[j][1] = Bs[cur][kr1][bn];
            }
#pragma unroll
            for (int i = 0; i < 2; i++)
#pragma unroll
                for (int j = 0; j < 4; j++) mma_tf32(acc[i][j], afr[i], bfr[j]);
        }
        if (t + 1 < ntiles) {
            const int nxt = cur ^ 1;
            float av[8] = {pa0.x, pa0.y, pa0.z, pa0.w, pa1.x, pa1.y, pa1.z, pa1.w};
            float bv[4] = {pb0.x, pb0.y, pb0.z, pb0.w};
#pragma unroll
            for (int q = 0; q < 8; q++) As[nxt][ak + q][arow] = to_tf32(av[q]);
#pragma unroll
            for (int q = 0; q < 4; q++) Bs[nxt][bk + q][brow] = to_tf32(bv[q]);
            __syncthreads();
        }
    }

#pragma unroll
    for (int i = 0; i < 2; i++) {
        const int r0 = m0 + wm * 32 + i * 16 + g;
        const int r1 = r0 + 8;
#pragma unroll
        for (int j = 0; j < 4; j++) {
            const int cidx = wn * 32 + j * 8 + 2 * kA;
            *(float2*)(g_xdbl + ((size_t)d * NR + r0) * NXDP + cidx) =
                make_float2(acc[i][j][0], acc[i][j][1]);
            *(float2*)(g_xdbl + ((size_t)d * NR + r1) * NXDP + cidx) =
                make_float2(acc[i][j][2], acc[i][j][3]);
        }
    }
}

// ---------------- K0: W_comb (fp16 output) ------------------------------------
__global__ __launch_bounds__(256) void k_wcomb(const float* __restrict__ Wproj,
                                               const float* __restrict__ Wout) {
    __shared__ float As[16 * 68];
    __shared__ float Bs[16 * 68];
    const int d = blockIdx.z;
    const int j0 = blockIdx.y * 64, c0 = blockIdx.x * 64;
    const int tid = threadIdx.x;
    const int tx = tid & 15, ty = tid >> 4;
    const int lm = tid >> 2, lk = (tid & 3) * 4;
    float acc[4][4];
#pragma unroll
    for (int i = 0; i < 4; i++)
#pragma unroll
        for (int j = 0; j < 4; j++) acc[i][j] = 0.f;

    for (int k0 = 0; k0 < DM; k0 += 16) {
        float4 av = *(const float4*)(Wproj + (size_t)(j0 + lm) * (4 * DM) + d * DM + k0 + lk);
        As[(lk + 0) * 68 + lm] = av.x;
        As[(lk + 1) * 68 + lm] = av.y;
        As[(lk + 2) * 68 + lm] = av.z;
        As[(lk + 3) * 68 + lm] = av.w;
#pragma unroll
        for (int pass = 0; pass < 4; pass++) {
            int idx = tid + pass * 256;
            int kk = idx >> 6, cc = idx & 63;
            Bs[kk * 68 + cc] = Wout[((size_t)d * DM + k0 + kk) * DI + c0 + cc];
        }
        __syncthreads();
#pragma unroll
        for (int kk = 0; kk < 16; kk++) {
            float4 a = *(const float4*)(As + kk * 68 + ty * 4);
            float4 b = *(const float4*)(Bs + kk * 68 + tx * 4);
            float am[4] = {a.x, a.y, a.z, a.w};
            float bm[4] = {b.x, b.y, b.z, b.w};
#pragma unroll
            for (int i = 0; i < 4; i++)
#pragma unroll
                for (int j = 0; j < 4; j++) acc[i][j] += am[i] * bm[j];
        }
        __syncthreads();
    }
#pragma unroll
    for (int i = 0; i < 4; i++) {
        __half2* dst = (__half2*)(g_wcomb16 + (size_t)(j0 + ty * 4 + i) * KCMB + d * DI + c0 + tx * 4);
        dst[0] = __floats2half2_rn(acc[i][0], acc[i][1]);
        dst[1] = __floats2half2_rn(acc[i][2], acc[i][3]);
    }
}

// ---------------- K2: depthwise causal conv (run-length 16) + SiLU -----------
__global__ __launch_bounds__(128) void k_conv2(const float* __restrict__ convw,
                                               const float* __restrict__ convb) {
    const int tid = threadIdx.x;
    const int c = blockIdx.x * 128 + tid;
    const int seg = blockIdx.y;
    const int bz = blockIdx.z;
    const int d = bz >> 3, b = bz & 7;
    const int p0 = seg * 16;

    float4 w4 = *(const float4*)(convw + ((size_t)d * DI + c) * 4);
    const float bias = convb[d * DI + c];
    const float* xzbase = g_xz + (size_t)b * SEQ * NJ + d * DXZ + c;

    float v[19];
#pragma unroll
    for (int j = 0; j < 19; j++) {
        int q = p0 + j - 3;
        v[j] = (q >= 0) ? xzbase[(size_t)orig_of_scan(d, q) * NJ] : 0.f;
    }
    float* ucp = g_uc + ((size_t)(d * 8 + b) * SEQ + p0) * DI + c;
#pragma unroll
    for (int k = 0; k < 16; k++) {
        float acc = bias + w4.x * v[k] + w4.y * v[k + 1] + w4.z * v[k + 2] + w4.w * v[k + 3];
        ucp[(size_t)k * DI] = __fdividef(acc, 1.f + __expf(-acc));
    }
}

// ---------------- K4a: scan pass1 — dq store + chunk summaries ---------------
__global__ __launch_bounds__(128) void k_scanP(const float* __restrict__ Alog,
                                               const float* __restrict__ Wdt,
                                               const float* __restrict__ bdt) {
    __shared__ __align__(16) float xs[2][8][NXDP];
    const int d = blockIdx.z;
    const int b = blockIdx.y >> 3, j = blockIdx.y & 7;
    const int tid = threadIdx.x;
    const int c = blockIdx.x * 128 + tid;
    const bool full = (j < 7);

    float w[24];
    {
        const float* wr = Wdt + ((size_t)d * DI + c) * 24;
#pragma unroll
        for (int q = 0; q < 6; q++) {
            float4 vv = *(const float4*)(wr + q * 4);
            w[q * 4] = vv.x; w[q * 4 + 1] = vv.y; w[q * 4 + 2] = vv.z; w[q * 4 + 3] = vv.w;
        }
    }
    const float bb = bdt[d * DI + c];
    float a[NSTATE];
#pragma unroll
    for (int n = 0; n < NSTATE; n++) a[n] = -__expf(Alog[((size_t)d * DI + c) * NSTATE + n]);
    bool structured = true;
#pragma unroll
    for (int n = 1; n < NSTATE; n++) {
        float e = (float)(n + 1) * a[0];
        if (fabsf(a[n] - e) > 1e-4f * fabsf(e) + 1e-12f) structured = false;
    }

    const int p0 = j * CHS;
    const size_t rbase = (size_t)d * NR + (size_t)b * SEQ + p0;
    const float* uptr = g_uc + rbase * DI + c;
    const float* xrowbase = g_xdbl + rbase * NXDP;
    float2* dqp = g_dq + rbase * DI + c;
    const int srow = tid >> 4, scol = (tid & 15) * 4;

    *(float4*)&xs[0][srow][scol] = *(const float4*)(xrowbase + (size_t)srow * NXDP + scol);
    float ucur[8], unxt[8];
#pragma unroll
    for (int k = 0; k < 8; k++) ucur[k] = uptr[(size_t)k * DI];
    __syncthreads();

    float h[NSTATE];
#pragma unroll
    for (int n = 0; n < NSTATE; n++) h[n] = 0.f;
    float S = 0.f;

    const int NCH = CHS / 8;
    for (int ch = 0; ch < NCH; ch++) {
        const int buf = ch & 1;
        const int pn = (ch + 1 < NCH) ? (ch + 1) * 8 : ch * 8;
        *(float4*)&xs[buf ^ 1][srow][scol] =
            *(const float4*)(xrowbase + (size_t)(pn + srow) * NXDP + scol);
#pragma unroll
        for (int k = 0; k < 8; k++) unxt[k] = uptr[(size_t)(pn + k) * DI];
        const int pl = ch * 8;
#pragma unroll
        for (int k = 0; k < 8; k++) {
            const float* row = &xs[buf][k][0];
            float s = bb;
#pragma unroll
            for (int q = 0; q < 6; q++) {
                float4 vv = *(const float4*)(row + q * 4);
                s += vv.x * w[q * 4] + vv.y * w[q * 4 + 1] + vv.z * w[q * 4 + 2] + vv.w * w[q * 4 + 3];
            }
            float es = __expf(s);
            float qv = __fdividef(1.f, 1.f + es);
            float delta = (s > 80.f) ? s : __logf(1.f + es);
            dqp[(size_t)(pl + k) * DI] = make_float2(delta, qv);
            if (full) {
                float dA[16];
                if (structured) {
                    float q2 = qv * qv, q4 = q2 * q2, q8 = q4 * q4;
                    dA[0] = qv;       dA[1] = q2;       dA[2] = q2 * qv;     dA[3] = q4;
                    dA[4] = q4 * qv;  dA[5] = q4 * q2;  dA[6] = q4 * dA[2];  dA[7] = q8;
                    dA[8] = q8 * qv;  dA[9] = q8 * q2;  dA[10] = q8 * dA[2]; dA[11] = q8 * q4;
                    dA[12] = q8 * dA[4]; dA[13] = q8 * dA[5]; dA[14] = q8 * dA[6]; dA[15] = q8 * q8;
                } else {
#pragma unroll
                    for (int n = 0; n < 16; n++) dA[n] = __expf(delta * a[n]);
                }
                float4 B0 = *(const float4*)(row + 24);
                float4 B1 = *(const float4*)(row + 28);
                float4 B2 = *(const float4*)(row + 32);
                float4 B3 = *(const float4*)(row + 36);
                float Bv[16] = {B0.x, B0.y, B0.z, B0.w, B1.x, B1.y, B1.z, B1.w,
                                B2.x, B2.y, B2.z, B2.w, B3.x, B3.y, B3.z, B3.w};
                const float du = delta * ucur[k];
                S += delta;
#pragma unroll
                for (int n = 0; n < 16; n++) h[n] = dA[n] * h[n] + du * Bv[n];
            }
        }
#pragma unroll
        for (int k = 0; k < 8; k++) ucur[k] = unxt[k];
        __syncthreads();
    }

    if (full) {
        float P[16];
        if (structured) {
            float qS = __expf(a[0] * S);
            float q2 = qS * qS, q4 = q2 * q2, q8 = q4 * q4;
            P[0] = qS;       P[1] = q2;       P[2] = q2 * qS;    P[3] = q4;
            P[4] = q4 * qS;  P[5] = q4 * q2;  P[6] = q4 * P[2];  P[7] = q8;
            P[8] = q8 * qS;  P[9] = q8 * q2;  P[10] = q8 * P[2]; P[11] = q8 * q4;
            P[12] = q8 * P[4]; P[13] = q8 * P[5]; P[14] = q8 * P[6]; P[15] = q8 * q8;
        } else {
#pragma unroll
            for (int n = 0; n < 16; n++) P[n] = __expf(a[n] * S);
        }
        const size_t obase = (((size_t)(d * 8 + b) * NCHUNK + j) * NSTATE) * DI + c;
#pragma unroll
        for (int n = 0; n < 16; n++) {
            g_chkP[obase + (size_t)n * DI] = P[n];
            g_chkH[obase + (size_t)n * DI] = h[n];
        }
    }
}

// ---------------- K4b: combine chunk states ----------------------------------
__global__ __launch_bounds__(256) void k_comb() {
    const int c = blockIdx.x * 256 + threadIdx.x;
    const int b = blockIdx.y, d = blockIdx.z;
    float h[NSTATE];
#pragma unroll
    for (int n = 0; n < NSTATE; n++) h[n] = 0.f;
    const size_t base = ((size_t)(d * 8 + b) * NCHUNK) * NSTATE * DI + c;
    for (int j = 0; j < NCHUNK; j++) {
        const size_t jb = base + (size_t)j * NSTATE * DI;
#pragma unroll
        for (int n = 0; n < NSTATE; n++) g_hin[jb + (size_t)n * DI] = h[n];
        if (j < NCHUNK - 1) {
#pragma unroll
            for (int n = 0; n < NSTATE; n++)
                h[n] = g_chkP[jb + (size_t)n * DI] * h[n] + g_chkH[jb + (size_t)n * DI];
        }
    }
}

// ---------------- K4c: scan pass2 — recurrence + output (fp16 yg store) ------
__global__ __launch_bounds__(128) void k_scan2(const float* __restrict__ Alog,
                                               const float* __restrict__ Dpar) {
    __shared__ __align__(16) float xs[2][8][32];   // B|C only
    const int d = blockIdx.z;
    const int b = blockIdx.y >> 3, j = blockIdx.y & 7;
    const int tid = threadIdx.x;
    const int c = blockIdx.x * 128 + tid;

    const float Dp = Dpar[d * DI + c];
    const size_t abase = ((size_t)d * DI + c) * NSTATE;
    float a0 = -__expf(Alog[abase]);
    bool structured = true;
#pragma unroll
    for (int n = 1; n < NSTATE; n++) {
        float an = -__expf(Alog[abase + n]);
        float e = (float)(n + 1) * a0;
        if (fabsf(an - e) > 1e-4f * fabsf(e) + 1e-12f) structured = false;
    }

    const int p0 = j * CHS;
    const size_t rbase = (size_t)d * NR + (size_t)b * SEQ + p0;
    const float* uptr = g_uc + rbase * DI + c;
    const float2* dqp = g_dq + rbase * DI + c;
    const float* zbase = g_xz + (size_t)b * SEQ * NJ + d * DXZ + DI + c;
    __half* ybase = g_yg16 + (size_t)b * SEQ * KCMB + (size_t)d * DI + c;
    const float* xrowbase = g_xdbl + rbase * NXDP + 24;

    float h[NSTATE];
    {
        const size_t hbase = (((size_t)(d * 8 + b) * NCHUNK + j) * NSTATE) * DI + c;
#pragma unroll
        for (int n = 0; n < NSTATE; n++) h[n] = g_hin[hbase + (size_t)n * DI];
    }

    const int srow = tid >> 3, scol = (tid & 7) * 4;
    if (tid < 64)
        *(float4*)&xs[0][srow][scol] = *(const float4*)(xrowbase + (size_t)srow * NXDP + scol);
    float ucur[8], zcur[8];
    float2 dqcur[8];
    float unxt[8], znxt[8];
    float2 dqnxt[8];
#pragma unroll
    for (int k = 0; k < 8; k++) {
        ucur[k] = uptr[(size_t)k * DI];
        dqcur[k] = dqp[(size_t)k * DI];
        zcur[k] = zbase[(size_t)orig_of_scan(d, p0 + k) * NJ];
    }
    __syncthreads();

    const int NCH = CHS / 8;
    for (int ch = 0; ch < NCH; ch++) {
        const int buf = ch & 1;
        const int pn = (ch + 1 < NCH) ? (ch + 1) * 8 : ch * 8;
        if (tid < 64)
            *(float4*)&xs[buf ^ 1][srow][scol] =
                *(const float4*)(xrowbase + (size_t)(pn + srow) * NXDP + scol);
#pragma unroll
        for (int k = 0; k < 8; k++) {
            unxt[k] = uptr[(size_t)(pn + k) * DI];
            dqnxt[k] = dqp[(size_t)(pn + k) * DI];
            znxt[k] = zbase[(size_t)orig_of_scan(d, p0 + pn + k) * NJ];
        }
        const int pl = ch * 8;
#pragma unroll
        for (int k = 0; k < 8; k++) {
            const float* row = &xs[buf][k][0];
            const float delta = dqcur[k].x;
            const float qv = dqcur[k].y;
            float dA[16];
            if (structured) {
                float q2 = qv * qv, q4 = q2 * q2, q8 = q4 * q4;
                dA[0] = qv;       dA[1] = q2;       dA[2] = q2 * qv;     dA[3] = q4;
                dA[4] = q4 * qv;  dA[5] = q4 * q2;  dA[6] = q4 * dA[2];  dA[7] = q8;
                dA[8] = q8 * qv;  dA[9] = q8 * q2;  dA[10] = q8 * dA[2]; dA[11] = q8 * q4;
                dA[12] = q8 * dA[4]; dA[13] = q8 * dA[5]; dA[14] = q8 * dA[6]; dA[15] = q8 * q8;
            } else {
#pragma unroll
                for (int n = 0; n < 16; n++)
                    dA[n] = __expf(delta * (-__expf(Alog[abase + n])));
            }
            float4 B0 = *(const float4*)(row + 0);
            float4 B1 = *(const float4*)(row + 4);
            float4 B2 = *(const float4*)(row + 8);
            float4 B3 = *(const float4*)(row + 12);
            float4 C0 = *(const float4*)(row + 16);
            float4 C1 = *(const float4*)(row + 20);
            float4 C2 = *(const float4*)(row + 24);
            float4 C3 = *(const float4*)(row + 28);
            float Bv[16] = {B0.x, B0.y, B0.z, B0.w, B1.x, B1.y, B1.z, B1.w,
                            B2.x, B2.y, B2.z, B2.w, B3.x, B3.y, B3.z, B3.w};
            float Cv[16] = {C0.x, C0.y, C0.z, C0.w, C1.x, C1.y, C1.z, C1.w,
                            C2.x, C2.y, C2.z, C2.w, C3.x, C3.y, C3.z, C3.w};
            const float u = ucur[k];
            const float du = delta * u;
            float acc0 = 0.f, acc1 = 0.f, acc2 = 0.f, acc3 = 0.f;
#pragma unroll
            for (int n = 0; n < 16; n += 4) {
                h[n] = dA[n] * h[n] + du * Bv[n];                 acc0 += h[n] * Cv[n];
                h[n + 1] = dA[n + 1] * h[n + 1] + du * Bv[n + 1]; acc1 += h[n + 1] * Cv[n + 1];
                h[n + 2] = dA[n + 2] * h[n + 2] + du * Bv[n + 2]; acc2 += h[n + 2] * Cv[n + 2];
                h[n + 3] = dA[n + 3] * h[n + 3] + du * Bv[n + 3]; acc3 += h[n + 3] * Cv[n + 3];
            }
            float y = (acc0 + acc1) + (acc2 + acc3) + u * Dp;
            float z = zcur[k];
            float sg = __fdividef(z, 1.f + __expf(-z));
            ybase[(size_t)orig_of_scan(d, p0 + pl + k) * KCMB] = __float2half_rn(y * sg);
        }
#pragma unroll
        for (int k = 0; k < 8; k++) {
            ucur[k] = unxt[k]; zcur[k] = znxt[k]; dqcur[k] = dqnxt[k];
        }
        __syncthreads();
    }
}

// ---------------- K6: LayerNorm ----------------------------------------------
__global__ __launch_bounds__(128) void k_ln(const float* __restrict__ gam,
                                            const float* __restrict__ bet,
                                            float* __restrict__ out) {
    const int r = blockIdx.x;
    const int tid = threadIdx.x;
    __shared__ float s1[4], s2[4];
    const float* row = g_r + (size_t)r * DM;
    float v0 = row[tid], v1 = row[tid + 128], v2 = row[tid + 256];
    float a = v0 + v1 + v2;
    float b = v0 * v0 + v1 * v1 + v2 * v2;
#pragma unroll
    for (int off = 16; off; off >>= 1) {
        a += __shfl_down_sync(0xffffffffu, a, off);
        b += __shfl_down_sync(0xffffffffu, b, off);
    }
    if ((tid & 31) == 0) { s1[tid >> 5] = a; s2[tid >> 5] = b; }
    __syncthreads();
    float ssum = s1[0] + s1[1] + s1[2] + s1[3];
    float ssq = s2[0] + s2[1] + s2[2] + s2[3];
    float mu = ssum * (1.f / 384.f);
    float var = ssq * (1.f / 384.f) - mu * mu;
    float rstd = rsqrtf(var + 1e-5f);
    out[(size_t)r * DM + tid] = gam[tid] * (v0 - mu) * rstd + bet[tid];
    out[(size_t)r * DM + tid + 128] = gam[tid + 128] * (v1 - mu) * rstd + bet[tid + 128];
    out[(size_t)r * DM + tid + 256] = gam[tid + 256] * (v2 - mu) * rstd + bet[tid + 256];
}

// ---------------- launch ------------------------------------------------------
extern "C" void kernel_launch(void* const* d_in, const int* in_sizes, int n_in,
                              void* d_out, int out_size) {
    const float* x = (const float*)d_in[0];
    const float* Win = (const float*)d_in[1];
    const float* convw = (const float*)d_in[2];
    const float* convb = (const float*)d_in[3];
    const float* Wx = (const float*)d_in[4];
    const float* Wdt = (const float*)d_in[5];
    const float* bdt = (const float*)d_in[6];
    const float* Alog = (const float*)d_in[7];
    const float* Dpar = (const float*)d_in[8];
    const float* Wout = (const float*)d_in[9];
    const float* Wproj = (const float*)d_in[10];
    const float* bproj = (const float*)d_in[11];
    const float* lng = (const float*)d_in[12];
    const float* lnb = (const float*)d_in[13];
    float* out = (float*)d_out;

    static float* p_xz = nullptr;
    static float* p_r = nullptr;
    static __half* p_x16 = nullptr;
    static __half* p_win16 = nullptr;
    static __half* p_wc16 = nullptr;
    static __half* p_yg16 = nullptr;
    if (!p_xz) {
        cudaGetSymbolAddress((void**)&p_xz, g_xz);
        cudaGetSymbolAddress((void**)&p_r, g_r);
        cudaGetSymbolAddress((void**)&p_x16, g_x16);
        cudaGetSymbolAddress((void**)&p_win16, g_win16);
        cudaGetSymbolAddress((void**)&p_wc16, g_wcomb16);
        cudaGetSymbolAddress((void**)&p_yg16, g_yg16);
    }

    const int nx4 = NR * DM / 4;
    const int nw4 = NJ * DM / 4;
    k_tohalf<<<(nx4 + 255) / 256, 256>>>((const float4*)x, (__half2*)p_x16, nx4);
    k_tohalf<<<(nw4 + 255) / 256, 256>>>((const float4*)Win, (__half2*)p_win16, nw4);
    k_wcomb<<<dim3(DI / 64, DM / 64, ND), 256>>>(Wproj, Wout);
    k_gemm_big<<<dim3(NJ / 128, NR / 128), 256>>>(p_x16, p_win16, p_xz, DM, NJ);
    k_conv2<<<dim3(DI / 128, SEQ / 16, ND * NB), 128>>>(convw, convb);
    k_xdbl_tf32<<<dim3(NR / 128, ND), 256>>>(Wx);
    k_scanP<<<dim3(DI / 128, NB * 8, ND), 128>>>(Alog, Wdt, bdt);
    k_comb<<<dim3(DI / 256, NB, ND), 256>>>();
    k_scan2<<<dim3(DI / 128, NB * 8, ND), 128>>>(Alog, Dpar);
    k_gemm_small<<<dim3(DM / 64, NR / 128), 128>>>(p_yg16, p_wc16, p_r, KCMB, DM, x, bproj);
    k_ln<<<NR, 128>>>(lng, lnb, out);
}

// round 16
// speedup vs baseline: 1.1756x; 1.0024x over previous
#include <cuda_runtime.h>
#include <cuda_fp16.h>
#include <math.h>
#include <stdint.h>

#define DM 384
#define DI 768
#define NSTATE 16
#define NB 8
#define SEQ 1024
#define ND 4
#define DXZ 1536          // 2*DI
#define NJ 6144           // ND*DXZ
#define NR 8192           // NB*SEQ rows
#define NXD 56            // dt_rank(24) + 2*16 (logical)
#define NXDP 64           // padded x_dbl row stride
#define KCMB 3072         // ND*DI combined K for output GEMM
#define NCHUNK 8
#define CHS 128           // steps per scan chunk

// ---------------- scratch (device globals; no cudaMalloc allowed) ------------
// g_xz layout: row (b*1024 + scan_pos_for_direction_d), col (d*1536 + c).
// i.e. each direction's 1536-col stripe is stored in ITS OWN scan order.
__device__ float g_xz[(size_t)NR * NJ];
__device__ float g_uc[(size_t)ND * NR * DI];      // post conv+silu (scan order)
__device__ float g_xdbl[(size_t)ND * NR * NXDP];  // [d][row][64] dt|B|C (padded)
__device__ float g_r[(size_t)NR * DM];            // pre-LN residual
__device__ float g_chkP[(size_t)ND * NB * NCHUNK * NSTATE * DI];
__device__ float g_chkH[(size_t)ND * NB * NCHUNK * NSTATE * DI];
__device__ float g_hin[(size_t)ND * NB * NCHUNK * NSTATE * DI];
__device__ float2 g_dq[(size_t)ND * NR * DI];     // packed {delta, exp(-delta)}
__device__ __half g_x16[(size_t)NR * DM];         // x in fp16
__device__ __half g_win16[(size_t)NJ * DM];       // W_in in fp16
__device__ __half g_wcomb16[(size_t)DM * KCMB];   // combined out-proj weight, fp16
__device__ __half g_yg16[(size_t)NR * KCMB];      // gated scan output, fp16, ORIGINAL order

// ---------------- cross-scan permutations ------------------------------------
__device__ __forceinline__ int orig_of_scan(int d, int p) {
    int hi = p >> 5, lo = p & 31;
    if (d == 0) return p;
    if (d == 1) return hi * 32 + (31 - lo);
    if (d == 2) return lo * 32 + hi;
    return (31 - lo) * 32 + hi;
}
__device__ __forceinline__ int scan_of_orig(int d, int l) {
    int h = l >> 5, w = l & 31;
    if (d == 0) return l;
    if (d == 1) return h * 32 + (31 - w);
    if (d == 2) return w * 32 + h;
    return w * 32 + (31 - h);
}

// ---------------- mma / cp.async helpers --------------------------------------
__device__ __forceinline__ uint32_t to_tf32(float x) {
    uint32_t r;
    asm("cvt.rna.tf32.f32 %0, %1;" : "=r"(r) : "f"(x));
    return r;
}
__device__ __forceinline__ void mma_tf32(float* c, const uint32_t* a, const uint32_t* b) {
    asm volatile(
        "mma.sync.aligned.m16n8k8.row.col.f32.tf32.tf32.f32 "
        "{%0,%1,%2,%3}, {%4,%5,%6,%7}, {%8,%9}, {%0,%1,%2,%3};"
        : "+f"(c[0]), "+f"(c[1]), "+f"(c[2]), "+f"(c[3])
        : "r"(a[0]), "r"(a[1]), "r"(a[2]), "r"(a[3]), "r"(b[0]), "r"(b[1]));
}
__device__ __forceinline__ void mma_fp16(float* c, const uint32_t* a, const uint32_t* b) {
    asm volatile(
        "mma.sync.aligned.m16n8k16.row.col.f32.f16.f16.f32 "
        "{%0,%1,%2,%3}, {%4,%5,%6,%7}, {%8,%9}, {%0,%1,%2,%3};"
        : "+f"(c[0]), "+f"(c[1]), "+f"(c[2]), "+f"(c[3])
        : "r"(a[0]), "r"(a[1]), "r"(a[2]), "r"(a[3]), "r"(b[0]), "r"(b[1]));
}
__device__ __forceinline__ void cpa16cg(void* sm, const void* g) {
    uint32_t sa = (uint32_t)__cvta_generic_to_shared(sm);
    asm volatile("cp.async.cg.shared.global [%0], [%1], 16;" :: "r"(sa), "l"(g));
}
#define CP_COMMIT() asm volatile("cp.async.commit_group;")
#define CP_WAIT2() asm volatile("cp.async.wait_group 2;")

// ---------------- prep: fp32 -> fp16 ------------------------------------------
__global__ __launch_bounds__(256) void k_tohalf(const float4* __restrict__ src,
                                                __half2* __restrict__ dst, int n4) {
    int i = blockIdx.x * 256 + threadIdx.x;
    if (i < n4) {
        float4 v = src[i];
        dst[2 * i] = __floats2half2_rn(v.x, v.y);
        dst[2 * i + 1] = __floats2half2_rn(v.z, v.w);
    }
}

// ---------------- K_GEMM big (FP16 mma, 256 thr, 128x128): inproj ------------
// Epilogue stores rows permuted to the direction's scan order.
__global__ __launch_bounds__(256, 2) void k_gemm_big(
    const __half* __restrict__ A, const __half* __restrict__ B,
    float* __restrict__ C, int K, int ldc) {
    __shared__ __align__(16) uint32_t As[4][128][12];
    __shared__ __align__(16) uint32_t Bs[4][128][12];
    const int tid = threadIdx.x;
    const int m0 = blockIdx.y * 128, n0 = blockIdx.x * 128;
    const int dd = blockIdx.x / 12;      // direction of this column block (1536/128=12)
    const int arow = tid & 127, au = (tid >> 7) * 4;
    const int lane = tid & 31, warp = tid >> 5;
    const int wm = warp >> 2, wn = warp & 3;
    const int g = lane >> 2, t = lane & 3;

    const __half* Ag = A + (size_t)(m0 + arow) * K + au * 2;
    const __half* Bg = B + (size_t)(n0 + arow) * K + au * 2;

    float acc[4][4][4];
#pragma unroll
    for (int i = 0; i < 4; i++)
#pragma unroll
        for (int j = 0; j < 4; j++)
#pragma unroll
            for (int q = 0; q < 4; q++) acc[i][j][q] = 0.f;

    const int nt = K >> 4;
#pragma unroll
    for (int s = 0; s < 3; s++) {
        cpa16cg(&As[s][arow][au], Ag + s * 16);
        cpa16cg(&Bs[s][arow][au], Bg + s * 16);
        CP_COMMIT();
    }

    for (int tt = 0; tt < nt; tt++) {
        CP_WAIT2();
        __syncthreads();
        const int st = tt & 3;
        uint32_t afr[4][4], bfr[4][2];
#pragma unroll
        for (int i = 0; i < 4; i++) {
            const int am = wm * 64 + i * 16 + g;
            afr[i][0] = As[st][am][t];
            afr[i][1] = As[st][am + 8][t];
            afr[i][2] = As[st][am][t + 4];
            afr[i][3] = As[st][am + 8][t + 4];
        }
#pragma unroll
        for (int j = 0; j < 4; j++) {
            const int bn = wn * 32 + j * 8 + g;
            bfr[j][0] = Bs[st][bn][t];
            bfr[j][1] = Bs[st][bn][t + 4];
        }
#pragma unroll
        for (int i = 0; i < 4; i++)
#pragma unroll
            for (int j = 0; j < 4; j++) mma_fp16(acc[i][j], afr[i], bfr[j]);
        const int tn = tt + 3;
        if (tn < nt) {
            cpa16cg(&As[tn & 3][arow][au], Ag + tn * 16);
            cpa16cg(&Bs[tn & 3][arow][au], Bg + tn * 16);
        }
        CP_COMMIT();
    }

#pragma unroll
    for (int i = 0; i < 4; i++) {
        const int r0 = m0 + wm * 64 + i * 16 + g;
        const int r1 = r0 + 8;
        const int p0r = (r0 & ~1023) + scan_of_orig(dd, r0 & 1023);
        const int p1r = (r1 & ~1023) + scan_of_orig(dd, r1 & 1023);
#pragma unroll
        for (int j = 0; j < 4; j++) {
            const int cidx = n0 + wn * 32 + j * 8 + 2 * t;
            *(float2*)(C + (size_t)p0r * ldc + cidx) = make_float2(acc[i][j][0], acc[i][j][1]);
            *(float2*)(C + (size_t)p1r * ldc + cidx) = make_float2(acc[i][j][2], acc[i][j][3]);
        }
    }
}

// ---------------- K_GEMM small (FP16 mma, 128 thr, 128x64): outproj ----------
__global__ __launch_bounds__(128, 4) void k_gemm_small(
    const __half* __restrict__ A, const __half* __restrict__ B,
    float* __restrict__ C, int K, int ldc,
    const float* __restrict__ X, const float* __restrict__ bias) {
    __shared__ __align__(16) uint32_t As[4][128][12];
    __shared__ __align__(16) uint32_t Bs[4][64][12];
    const int tid = threadIdx.x;
    const int m0 = blockIdx.y * 128, n0 = blockIdx.x * 64;
    const int lane = tid & 31, warp = tid >> 5;
    const int wm = warp >> 1, wn = warp & 1;
    const int g = lane >> 2, t = lane & 3;

    const __half* Ag = A + (size_t)(m0 + tid) * K;
    const __half* Bg = B + (size_t)(n0 + (tid & 63)) * K;
    const bool bldr = (tid < 64);

    float acc[4][4][4];
#pragma unroll
    for (int i = 0; i < 4; i++)
#pragma unroll
        for (int j = 0; j < 4; j++)
#pragma unroll
            for (int q = 0; q < 4; q++) acc[i][j][q] = 0.f;

    const int nt = K >> 4;
#pragma unroll
    for (int s = 0; s < 3; s++) {
        cpa16cg(&As[s][tid][0], Ag + s * 16);
        cpa16cg(&As[s][tid][4], Ag + s * 16 + 8);
        if (bldr) {
            cpa16cg(&Bs[s][tid][0], Bg + s * 16);
            cpa16cg(&Bs[s][tid][4], Bg + s * 16 + 8);
        }
        CP_COMMIT();
    }

    for (int tt = 0; tt < nt; tt++) {
        CP_WAIT2();
        __syncthreads();
        const int st = tt & 3;
        uint32_t afr[4][4], bfr[4][2];
#pragma unroll
        for (int i = 0; i < 4; i++) {
            const int am = wm * 64 + i * 16 + g;
            afr[i][0] = As[st][am][t];
            afr[i][1] = As[st][am + 8][t];
            afr[i][2] = As[st][am][t + 4];
            afr[i][3] = As[st][am + 8][t + 4];
        }
#pragma unroll
        for (int j = 0; j < 4; j++) {
            const int bn = wn * 32 + j * 8 + g;
            bfr[j][0] = Bs[st][bn][t];
            bfr[j][1] = Bs[st][bn][t + 4];
        }
#pragma unroll
        for (int i = 0; i < 4; i++)
#pragma unroll
            for (int j = 0; j < 4; j++) mma_fp16(acc[i][j], afr[i], bfr[j]);
        const int tn = tt + 3;
        if (tn < nt) {
            cpa16cg(&As[tn & 3][tid][0], Ag + tn * 16);
            cpa16cg(&As[tn & 3][tid][4], Ag + tn * 16 + 8);
            if (bldr) {
                cpa16cg(&Bs[tn & 3][tid][0], Bg + tn * 16);
                cpa16cg(&Bs[tn & 3][tid][4], Bg + tn * 16 + 8);
            }
        }
        CP_COMMIT();
    }

#pragma unroll
    for (int i = 0; i < 4; i++) {
        const int r0 = m0 + wm * 64 + i * 16 + g;
        const int r1 = r0 + 8;
#pragma unroll
        for (int j = 0; j < 4; j++) {
            const int cidx = n0 + wn * 32 + j * 8 + 2 * t;
            float2 s0 = make_float2(acc[i][j][0], acc[i][j][1]);
            float2 s1 = make_float2(acc[i][j][2], acc[i][j][3]);
            float2 x0 = *(const float2*)(X + (size_t)r0 * DM + cidx);
            float2 x1 = *(const float2*)(X + (size_t)r1 * DM + cidx);
            float2 bb = *(const float2*)(bias + cidx);
            s0.x += x0.x + bb.x; s0.y += x0.y + bb.y;
            s1.x += x1.x + bb.x; s1.y += x1.y + bb.y;
            *(float2*)(C + (size_t)r0 * ldc + cidx) = s0;
            *(float2*)(C + (size_t)r1 * ldc + cidx) = s1;
        }
    }
}

// ---------------- K3: x_dbl (TF32 mma): per d, [8192x768]@[56x768]^T ---------
__global__ __launch_bounds__(256) void k_xdbl_tf32(const float* __restrict__ Wx) {
    __shared__ __align__(16) uint32_t As[2][16][136];
    __shared__ __align__(16) uint32_t Bs[2][16][72];
    const int tid = threadIdx.x;
    const int d = blockIdx.y;
    const int m0 = blockIdx.x * 128;
    const float* Auc = g_uc + (size_t)d * NR * DI;
    const float* Bw = Wx + (size_t)d * NXD * DI;

    const int arow = tid & 127, ak = (tid >> 7) * 8;
    const int brow = tid & 63, bk = (tid >> 6) * 4;
    const int lane = tid & 31, warp = tid >> 5;
    const int wm = warp >> 1, wn = warp & 1;
    const int g = lane >> 2, kA = lane & 3;

    const float* Ag = Auc + (size_t)(m0 + arow) * DI + ak;
    const float* Bg = Bw + (size_t)brow * DI + bk;
    const bool bvalid = (brow < NXD);

    float acc[2][4][4];
#pragma unroll
    for (int i = 0; i < 2; i++)
#pragma unroll
        for (int j = 0; j < 4; j++)
#pragma unroll
            for (int q = 0; q < 4; q++) acc[i][j][q] = 0.f;

    const int ntiles = DI >> 4;
    float4 pa0, pa1, pb0;
    pa0 = *(const float4*)(Ag);
    pa1 = *(const float4*)(Ag + 4);
    pb0 = bvalid ? *(const float4*)(Bg) : make_float4(0.f, 0.f, 0.f, 0.f);
    {
        float av[8] = {pa0.x, pa0.y, pa0.z, pa0.w, pa1.x, pa1.y, pa1.z, pa1.w};
        float bv[4] = {pb0.x, pb0.y, pb0.z, pb0.w};
#pragma unroll
        for (int q = 0; q < 8; q++) As[0][ak + q][arow] = to_tf32(av[q]);
#pragma unroll
        for (int q = 0; q < 4; q++) Bs[0][bk + q][brow] = to_tf32(bv[q]);
    }
    __syncthreads();

    for (int t = 0; t < ntiles; t++) {
        const int cur = t & 1;
        if (t + 1 < ntiles) {
            const int k0 = (t + 1) << 4;
            pa0 = *(const float4*)(Ag + k0);
            pa1 = *(const float4*)(Ag + k0 + 4);
            pb0 = bvalid ? *(const float4*)(Bg + k0) : make_float4(0.f, 0.f, 0.f, 0.f);
        }
#pragma unroll
        for (int k8 = 0; k8 < 16; k8 += 8) {
            uint32_t afr[2][4], bfr[4][2];
            const int kr0 = k8 + kA, kr1 = k8 + kA + 4;
#pragma unroll
            for (int i = 0; i < 2; i++) {
                const int am = wm * 32 + i * 16 + g;
                afr[i][0] = As[cur][kr0][am];
                afr[i][1] = As[cur][kr0][am + 8];
                afr[i][2] = As[cur][kr1][am];
                afr[i][3] = As[cur][kr1][am + 8];
            }
#pragma unroll
            for (int j = 0; j < 4; j++) {
                const int bn = wn * 32 + j * 8 + g;
                bfr[j][0] = Bs[cur][kr0][bn];
                bfr[j][1] = Bs[cur][kr1][bn];
            }
#pragma unroll
            for (int i = 0; i < 2; i++)
#pragma unroll
                for (int j = 0; j < 4; j++) mma_tf32(acc[i][j], afr[i], bfr[j]);
        }
        if (t + 1 < ntiles) {
            const int nxt = cur ^ 1;
            float av[8] = {pa0.x, pa0.y, pa0.z, pa0.w, pa1.x, pa1.y, pa1.z, pa1.w};
            float bv[4] = {pb0.x, pb0.y, pb0.z, pb0.w};
#pragma unroll
            for (int q = 0; q < 8; q++) As[nxt][ak + q][arow] = to_tf32(av[q]);
#pragma unroll
            for (int q = 0; q < 4; q++) Bs[nxt][bk + q][brow] = to_tf32(bv[q]);
            __syncthreads();
        }
    }

#pragma unroll
    for (int i = 0; i < 2; i++) {
        const int r0 = m0 + wm * 32 + i * 16 + g;
        const int r1 = r0 + 8;
#pragma unroll
        for (int j = 0; j < 4; j++) {
            const int cidx = wn * 32 + j * 8 + 2 * kA;
            *(float2*)(g_xdbl + ((size_t)d * NR + r0) * NXDP + cidx) =
                make_float2(acc[i][j][0], acc[i][j][1]);
            *(float2*)(g_xdbl + ((size_t)d * NR + r1) * NXDP + cidx) =
                make_float2(acc[i][j][2], acc[i][j][3]);
        }
    }
}

// ---------------- K0: W_comb (fp16 output) ------------------------------------
__global__ __launch_bounds__(256) void k_wcomb(const float* __restrict__ Wproj,
                                               const float* __restrict__ Wout) {
    __shared__ float As[16 * 68];
    __shared__ float Bs[16 * 68];
    const int d = blockIdx.z;
    const int j0 = blockIdx.y * 64, c0 = blockIdx.x * 64;
    const int tid = threadIdx.x;
    const int tx = tid & 15, ty = tid >> 4;
    const int lm = tid >> 2, lk = (tid & 3) * 4;
    float acc[4][4];
#pragma unroll
    for (int i = 0; i < 4; i++)
#pragma unroll
        for (int j = 0; j < 4; j++) acc[i][j] = 0.f;

    for (int k0 = 0; k0 < DM; k0 += 16) {
        float4 av = *(const float4*)(Wproj + (size_t)(j0 + lm) * (4 * DM) + d * DM + k0 + lk);
        As[(lk + 0) * 68 + lm] = av.x;
        As[(lk + 1) * 68 + lm] = av.y;
        As[(lk + 2) * 68 + lm] = av.z;
        As[(lk + 3) * 68 + lm] = av.w;
#pragma unroll
        for (int pass = 0; pass < 4; pass++) {
            int idx = tid + pass * 256;
            int kk = idx >> 6, cc = idx & 63;
            Bs[kk * 68 + cc] = Wout[((size_t)d * DM + k0 + kk) * DI + c0 + cc];
        }
        __syncthreads();
#pragma unroll
        for (int kk = 0; kk < 16; kk++) {
            float4 a = *(const float4*)(As + kk * 68 + ty * 4);
            float4 b = *(const float4*)(Bs + kk * 68 + tx * 4);
            float am[4] = {a.x, a.y, a.z, a.w};
            float bm[4] = {b.x, b.y, b.z, b.w};
#pragma unroll
            for (int i = 0; i < 4; i++)
#pragma unroll
                for (int j = 0; j < 4; j++) acc[i][j] += am[i] * bm[j];
        }
        __syncthreads();
    }
#pragma unroll
    for (int i = 0; i < 4; i++) {
        __half2* dst = (__half2*)(g_wcomb16 + (size_t)(j0 + ty * 4 + i) * KCMB + d * DI + c0 + tx * 4);
        dst[0] = __floats2half2_rn(acc[i][0], acc[i][1]);
        dst[1] = __floats2half2_rn(acc[i][2], acc[i][3]);
    }
}

// ---------------- K2: depthwise causal conv (sequential scan rows) + SiLU ----
__global__ __launch_bounds__(128) void k_conv2(const float* __restrict__ convw,
                                               const float* __restrict__ convb) {
    const int tid = threadIdx.x;
    const int c = blockIdx.x * 128 + tid;
    const int seg = blockIdx.y;
    const int bz = blockIdx.z;
    const int d = bz >> 3, b = bz & 7;
    const int p0 = seg * 16;

    float4 w4 = *(const float4*)(convw + ((size_t)d * DI + c) * 4);
    const float bias = convb[d * DI + c];
    const float* xzbase = g_xz + (size_t)b * SEQ * NJ + d * DXZ + c;  // rows = scan order

    float v[19];
#pragma unroll
    for (int j = 0; j < 19; j++) {
        int q = p0 + j - 3;
        v[j] = (q >= 0) ? xzbase[(size_t)q * NJ] : 0.f;
    }
    float* ucp = g_uc + ((size_t)(d * 8 + b) * SEQ + p0) * DI + c;
#pragma unroll
    for (int k = 0; k < 16; k++) {
        float acc = bias + w4.x * v[k] + w4.y * v[k + 1] + w4.z * v[k + 2] + w4.w * v[k + 3];
        ucp[(size_t)k * DI] = __fdividef(acc, 1.f + __expf(-acc));
    }
}

// ---------------- K4a: scan pass1 — dq store + chunk summaries ---------------
__global__ __launch_bounds__(128) void k_scanP(const float* __restrict__ Alog,
                                               const float* __restrict__ Wdt,
                                               const float* __restrict__ bdt) {
    __shared__ __align__(16) float xs[2][8][NXDP];
    const int d = blockIdx.z;
    const int b = blockIdx.y >> 3, j = blockIdx.y & 7;
    const int tid = threadIdx.x;
    const int c = blockIdx.x * 128 + tid;
    const bool full = (j < 7);

    float w[24];
    {
        const float* wr = Wdt + ((size_t)d * DI + c) * 24;
#pragma unroll
        for (int q = 0; q < 6; q++) {
            float4 vv = *(const float4*)(wr + q * 4);
            w[q * 4] = vv.x; w[q * 4 + 1] = vv.y; w[q * 4 + 2] = vv.z; w[q * 4 + 3] = vv.w;
        }
    }
    const float bb = bdt[d * DI + c];
    float a[NSTATE];
#pragma unroll
    for (int n = 0; n < NSTATE; n++) a[n] = -__expf(Alog[((size_t)d * DI + c) * NSTATE + n]);
    bool structured = true;
#pragma unroll
    for (int n = 1; n < NSTATE; n++) {
        float e = (float)(n + 1) * a[0];
        if (fabsf(a[n] - e) > 1e-4f * fabsf(e) + 1e-12f) structured = false;
    }

    const int p0 = j * CHS;
    const size_t rbase = (size_t)d * NR + (size_t)b * SEQ + p0;
    const float* uptr = g_uc + rbase * DI + c;
    const float* xrowbase = g_xdbl + rbase * NXDP;
    float2* dqp = g_dq + rbase * DI + c;
    const int srow = tid >> 4, scol = (tid & 15) * 4;

    *(float4*)&xs[0][srow][scol] = *(const float4*)(xrowbase + (size_t)srow * NXDP + scol);
    float ucur[8], unxt[8];
#pragma unroll
    for (int k = 0; k < 8; k++) ucur[k] = uptr[(size_t)k * DI];
    __syncthreads();

    float h[NSTATE];
#pragma unroll
    for (int n = 0; n < NSTATE; n++) h[n] = 0.f;
    float S = 0.f;

    const int NCH = CHS / 8;
    for (int ch = 0; ch < NCH; ch++) {
        const int buf = ch & 1;
        const int pn = (ch + 1 < NCH) ? (ch + 1) * 8 : ch * 8;
        *(float4*)&xs[buf ^ 1][srow][scol] =
            *(const float4*)(xrowbase + (size_t)(pn + srow) * NXDP + scol);
#pragma unroll
        for (int k = 0; k < 8; k++) unxt[k] = uptr[(size_t)(pn + k) * DI];
        const int pl = ch * 8;
#pragma unroll
        for (int k = 0; k < 8; k++) {
            const float* row = &xs[buf][k][0];
            float s = bb;
#pragma unroll
            for (int q = 0; q < 6; q++) {
                float4 vv = *(const float4*)(row + q * 4);
                s += vv.x * w[q * 4] + vv.y * w[q * 4 + 1] + vv.z * w[q * 4 + 2] + vv.w * w[q * 4 + 3];
            }
            float es = __expf(s);
            float qv = __fdividef(1.f, 1.f + es);
            float delta = (s > 80.f) ? s : __logf(1.f + es);
            dqp[(size_t)(pl + k) * DI] = make_float2(delta, qv);
            if (full) {
                float dA[16];
                if (structured) {
                    float q2 = qv * qv, q4 = q2 * q2, q8 = q4 * q4;
                    dA[0] = qv;       dA[1] = q2;       dA[2] = q2 * qv;     dA[3] = q4;
                    dA[4] = q4 * qv;  dA[5] = q4 * q2;  dA[6] = q4 * dA[2];  dA[7] = q8;
                    dA[8] = q8 * qv;  dA[9] = q8 * q2;  dA[10] = q8 * dA[2]; dA[11] = q8 * q4;
                    dA[12] = q8 * dA[4]; dA[13] = q8 * dA[5]; dA[14] = q8 * dA[6]; dA[15] = q8 * q8;
                } else {
#pragma unroll
                    for (int n = 0; n < 16; n++) dA[n] = __expf(delta * a[n]);
                }
                float4 B0 = *(const float4*)(row + 24);
                float4 B1 = *(const float4*)(row + 28);
                float4 B2 = *(const float4*)(row + 32);
                float4 B3 = *(const float4*)(row + 36);
                float Bv[16] = {B0.x, B0.y, B0.z, B0.w, B1.x, B1.y, B1.z, B1.w,
                                B2.x, B2.y, B2.z, B2.w, B3.x, B3.y, B3.z, B3.w};
                const float du = delta * ucur[k];
                S += delta;
#pragma unroll
                for (int n = 0; n < 16; n++) h[n] = dA[n] * h[n] + du * Bv[n];
            }
        }
#pragma unroll
        for (int k = 0; k < 8; k++) ucur[k] = unxt[k];
        __syncthreads();
    }

    if (full) {
        float P[16];
        if (structured) {
            float qS = __expf(a[0] * S);
            float q2 = qS * qS, q4 = q2 * q2, q8 = q4 * q4;
            P[0] = qS;       P[1] = q2;       P[2] = q2 * qS;    P[3] = q4;
            P[4] = q4 * qS;  P[5] = q4 * q2;  P[6] = q4 * P[2];  P[7] = q8;
            P[8] = q8 * qS;  P[9] = q8 * q2;  P[10] = q8 * P[2]; P[11] = q8 * q4;
            P[12] = q8 * P[4]; P[13] = q8 * P[5]; P[14] = q8 * P[6]; P[15] = q8 * q8;
        } else {
#pragma unroll
            for (int n = 0; n < 16; n++) P[n] = __expf(a[n] * S);
        }
        const size_t obase = (((size_t)(d * 8 + b) * NCHUNK + j) * NSTATE) * DI + c;
#pragma unroll
        for (int n = 0; n < 16; n++) {
            g_chkP[obase + (size_t)n * DI] = P[n];
            g_chkH[obase + (size_t)n * DI] = h[n];
        }
    }
}

// ---------------- K4b: combine chunk states ----------------------------------
__global__ __launch_bounds__(256) void k_comb() {
    const int c = blockIdx.x * 256 + threadIdx.x;
    const int b = blockIdx.y, d = blockIdx.z;
    float h[NSTATE];
#pragma unroll
    for (int n = 0; n < NSTATE; n++) h[n] = 0.f;
    const size_t base = ((size_t)(d * 8 + b) * NCHUNK) * NSTATE * DI + c;
    for (int j = 0; j < NCHUNK; j++) {
        const size_t jb = base + (size_t)j * NSTATE * DI;
#pragma unroll
        for (int n = 0; n < NSTATE; n++) g_hin[jb + (size_t)n * DI] = h[n];
        if (j < NCHUNK - 1) {
#pragma unroll
            for (int n = 0; n < NSTATE; n++)
                h[n] = g_chkP[jb + (size_t)n * DI] * h[n] + g_chkH[jb + (size_t)n * DI];
        }
    }
}

// ---------------- K4c: scan pass2 — recurrence + output (fp16 yg store) ------
__global__ __launch_bounds__(128) void k_scan2(const float* __restrict__ Alog,
                                               const float* __restrict__ Dpar) {
    __shared__ __align__(16) float xs[2][8][32];   // B|C only
    const int d = blockIdx.z;
    const int b = blockIdx.y >> 3, j = blockIdx.y & 7;
    const int tid = threadIdx.x;
    const int c = blockIdx.x * 128 + tid;

    const float Dp = Dpar[d * DI + c];
    const size_t abase = ((size_t)d * DI + c) * NSTATE;
    float a0 = -__expf(Alog[abase]);
    bool structured = true;
#pragma unroll
    for (int n = 1; n < NSTATE; n++) {
        float an = -__expf(Alog[abase + n]);
        float e = (float)(n + 1) * a0;
        if (fabsf(an - e) > 1e-4f * fabsf(e) + 1e-12f) structured = false;
    }

    const int p0 = j * CHS;
    const size_t rbase = (size_t)d * NR + (size_t)b * SEQ + p0;
    const float* uptr = g_uc + rbase * DI + c;
    const float2* dqp = g_dq + rbase * DI + c;
    // z now stored in scan order: linear index in p
    const float* zbase = g_xz + ((size_t)b * SEQ + p0) * NJ + d * DXZ + DI + c;
    __half* ybase = g_yg16 + (size_t)b * SEQ * KCMB + (size_t)d * DI + c;
    const float* xrowbase = g_xdbl + rbase * NXDP + 24;

    float h[NSTATE];
    {
        const size_t hbase = (((size_t)(d * 8 + b) * NCHUNK + j) * NSTATE) * DI + c;
#pragma unroll
        for (int n = 0; n < NSTATE; n++) h[n] = g_hin[hbase + (size_t)n * DI];
    }

    const int srow = tid >> 3, scol = (tid & 7) * 4;
    if (tid < 64)
        *(float4*)&xs[0][srow][scol] = *(const float4*)(xrowbase + (size_t)srow * NXDP + scol);
    float ucur[8], zcur[8];
    float2 dqcur[8];
    float unxt[8], znxt[8];
    float2 dqnxt[8];
#pragma unroll
    for (int k = 0; k < 8; k++) {
        ucur[k] = uptr[(size_t)k * DI];
        dqcur[k] = dqp[(size_t)k * DI];
        zcur[k] = zbase[(size_t)k * NJ];
    }
    __syncthreads();

    const int NCH = CHS / 8;
    for (int ch = 0; ch < NCH; ch++) {
        const int buf = ch & 1;
        const int pn = (ch + 1 < NCH) ? (ch + 1) * 8 : ch * 8;
        if (tid < 64)
            *(float4*)&xs[buf ^ 1][srow][scol] =
                *(const float4*)(xrowbase + (size_t)(pn + srow) * NXDP + scol);
#pragma unroll
        for (int k = 0; k < 8; k++) {
            unxt[k] = uptr[(size_t)(pn + k) * DI];
            dqnxt[k] = dqp[(size_t)(pn + k) * DI];
            znxt[k] = zbase[(size_t)(pn + k) * NJ];
        }
        const int pl = ch * 8;
#pragma unroll
        for (int k = 0; k < 8; k++) {
            const float* row = &xs[buf][k][0];
            const float delta = dqcur[k].x;
            const float qv = dqcur[k].y;
            float dA[16];
            if (structured) {
                float q2 = qv * qv, q4 = q2 * q2, q8 = q4 * q4;
                dA[0] = qv;       dA[1] = q2;       dA[2] = q2 * qv;     dA[3] = q4;
                dA[4] = q4 * qv;  dA[5] = q4 * q2;  dA[6] = q4 * dA[2];  dA[7] = q8;
                dA[8] = q8 * qv;  dA[9] = q8 * q2;  dA[10] = q8 * dA[2]; dA[11] = q8 * q4;
                dA[12] = q8 * dA[4]; dA[13] = q8 * dA[5]; dA[14] = q8 * dA[6]; dA[15] = q8 * q8;
            } else {
#pragma unroll
                for (int n = 0; n < 16; n++)
                    dA[n] = __expf(delta * (-__expf(Alog[abase + n])));
            }
            float4 B0 = *(const float4*)(row + 0);
            float4 B1 = *(const float4*)(row + 4);
            float4 B2 = *(const float4*)(row + 8);
            float4 B3 = *(const float4*)(row + 12);
            float4 C0 = *(const float4*)(row + 16);
            float4 C1 = *(const float4*)(row + 20);
            float4 C2 = *(const float4*)(row + 24);
            float4 C3 = *(const float4*)(row + 28);
            float Bv[16] = {B0.x, B0.y, B0.z, B0.w, B1.x, B1.y, B1.z, B1.w,
                            B2.x, B2.y, B2.z, B2.w, B3.x, B3.y, B3.z, B3.w};
            float Cv[16] = {C0.x, C0.y, C0.z, C0.w, C1.x, C1.y, C1.z, C1.w,
                            C2.x, C2.y, C2.z, C2.w, C3.x, C3.y, C3.z, C3.w};
            const float u = ucur[k];
            const float du = delta * u;
            float acc0 = 0.f, acc1 = 0.f, acc2 = 0.f, acc3 = 0.f;
#pragma unroll
            for (int n = 0; n < 16; n += 4) {
                h[n] = dA[n] * h[n] + du * Bv[n];                 acc0 += h[n] * Cv[n];
                h[n + 1] = dA[n + 1] * h[n + 1] + du * Bv[n + 1]; acc1 += h[n + 1] * Cv[n + 1];
                h[n + 2] = dA[n + 2] * h[n + 2] + du * Bv[n + 2]; acc2 += h[n + 2] * Cv[n + 2];
                h[n + 3] = dA[n + 3] * h[n + 3] + du * Bv[n + 3]; acc3 += h[n + 3] * Cv[n + 3];
            }
            float y = (acc0 + acc1) + (acc2 + acc3) + u * Dp;
            float z = zcur[k];
            float sg = __fdividef(z, 1.f + __expf(-z));
            ybase[(size_t)orig_of_scan(d, p0 + pl + k) * KCMB] = __float2half_rn(y * sg);
        }
#pragma unroll
        for (int k = 0; k < 8; k++) {
            ucur[k] = unxt[k]; zcur[k] = znxt[k]; dqcur[k] = dqnxt[k];
        }
        __syncthreads();
    }
}

// ---------------- K6: LayerNorm ----------------------------------------------
__global__ __launch_bounds__(128) void k_ln(const float* __restrict__ gam,
                                            const float* __restrict__ bet,
                                            float* __restrict__ out) {
    const int r = blockIdx.x;
    const int tid = threadIdx.x;
    __shared__ float s1[4], s2[4];
    const float* row = g_r + (size_t)r * DM;
    float v0 = row[tid], v1 = row[tid + 128], v2 = row[tid + 256];
    float a = v0 + v1 + v2;
    float b = v0 * v0 + v1 * v1 + v2 * v2;
#pragma unroll
    for (int off = 16; off; off >>= 1) {
        a += __shfl_down_sync(0xffffffffu, a, off);
        b += __shfl_down_sync(0xffffffffu, b, off);
    }
    if ((tid & 31) == 0) { s1[tid >> 5] = a; s2[tid >> 5] = b; }
    __syncthreads();
    float ssum = s1[0] + s1[1] + s1[2] + s1[3];
    float ssq = s2[0] + s2[1] + s2[2] + s2[3];
    float mu = ssum * (1.f / 384.f);
    float var = ssq * (1.f / 384.f) - mu * mu;
    float rstd = rsqrtf(var + 1e-5f);
    out[(size_t)r * DM + tid] = gam[tid] * (v0 - mu) * rstd + bet[tid];
    out[(size_t)r * DM + tid + 128] = gam[tid + 128] * (v1 - mu) * rstd + bet[tid + 128];
    out[(size_t)r * DM + tid + 256] = gam[tid + 256] * (v2 - mu) * rstd + bet[tid + 256];
}

// ---------------- launch ------------------------------------------------------
extern "C" void kernel_launch(void* const* d_in, const int* in_sizes, int n_in,
                              void* d_out, int out_size) {
    const float* x = (const float*)d_in[0];
    const float* Win = (const float*)d_in[1];
    const float* convw = (const float*)d_in[2];
    const float* convb = (const float*)d_in[3];
    const float* Wx = (const float*)d_in[4];
    const float* Wdt = (const float*)d_in[5];
    const float* bdt = (const float*)d_in[6];
    const float* Alog = (const float*)d_in[7];
    const float* Dpar = (const float*)d_in[8];
    const float* Wout = (const float*)d_in[9];
    const float* Wproj = (const float*)d_in[10];
    const float* bproj = (const float*)d_in[11];
    const float* lng = (const float*)d_in[12];
    const float* lnb = (const float*)d_in[13];
    float* out = (float*)d_out;

    static float* p_xz = nullptr;
    static float* p_r = nullptr;
    static __half* p_x16 = nullptr;
    static __half* p_win16 = nullptr;
    static __half* p_wc16 = nullptr;
    static __half* p_yg16 = nullptr;
    if (!p_xz) {
        cudaGetSymbolAddress((void**)&p_xz, g_xz);
        cudaGetSymbolAddress((void**)&p_r, g_r);
        cudaGetSymbolAddress((void**)&p_x16, g_x16);
        cudaGetSymbolAddress((void**)&p_win16, g_win16);
        cudaGetSymbolAddress((void**)&p_wc16, g_wcomb16);
        cudaGetSymbolAddress((void**)&p_yg16, g_yg16);
    }

    const int nx4 = NR * DM / 4;
    const int nw4 = NJ * DM / 4;
    k_tohalf<<<(nx4 + 255) / 256, 256>>>((const float4*)x, (__half2*)p_x16, nx4);
    k_tohalf<<<(nw4 + 255) / 256, 256>>>((const float4*)Win, (__half2*)p_win16, nw4);
    k_wcomb<<<dim3(DI / 64, DM / 64, ND), 256>>>(Wproj, Wout);
    k_gemm_big<<<dim3(NJ / 128, NR / 128), 256>>>(p_x16, p_win16, p_xz, DM, NJ);
    k_conv2<<<dim3(DI / 128, SEQ / 16, ND * NB), 128>>>(convw, convb);
    k_xdbl_tf32<<<dim3(NR / 128, ND), 256>>>(Wx);
    k_scanP<<<dim3(DI / 128, NB * 8, ND), 128>>>(Alog, Wdt, bdt);
    k_comb<<<dim3(DI / 256, NB, ND), 256>>>();
    k_scan2<<<dim3(DI / 128, NB * 8, ND), 128>>>(Alog, Dpar);
    k_gemm_small<<<dim3(DM / 64, NR / 128), 128>>>(p_yg16, p_wc16, p_r, KCMB, DM, x, bproj);
    k_ln<<<NR, 128>>>(lng, lnb, out);
}

// round 17
// speedup vs baseline: 1.2050x; 1.0250x over previous
#include <cuda_runtime.h>
#include <cuda_fp16.h>
#include <math.h>
#include <stdint.h>

#define DM 384
#define DI 768
#define NSTATE 16
#define NB 8
#define SEQ 1024
#define ND 4
#define DXZ 1536          // 2*DI
#define NJ 6144           // ND*DXZ
#define NR 8192           // NB*SEQ rows
#define NXD 56            // dt_rank(24) + 2*16 (logical)
#define NXDP 64           // padded x_dbl row stride
#define KCMB 3072         // ND*DI combined K for output GEMM
#define NCHUNK 8
#define CHS 128           // steps per scan chunk

// ---------------- scratch (device globals; no cudaMalloc allowed) ------------
// g_xz layout: row (b*1024 + scan_pos_for_direction_d), col (d*1536 + c).
__device__ float g_xz[(size_t)NR * NJ];
__device__ float g_uc[(size_t)ND * NR * DI];      // post conv+silu (scan order)
__device__ float g_xdbl[(size_t)ND * NR * NXDP];  // [d][row][64] dt|B|C (padded)
__device__ float g_r[(size_t)NR * DM];            // pre-LN residual
__device__ float g_chkP[(size_t)ND * NB * NCHUNK * NSTATE * DI];
__device__ float g_chkH[(size_t)ND * NB * NCHUNK * NSTATE * DI];
__device__ float g_hin[(size_t)ND * NB * NCHUNK * NSTATE * DI];
__device__ float2 g_dq[(size_t)ND * NR * DI];     // packed {delta, exp(-delta)}
__device__ __half g_x16[(size_t)NR * DM];         // x in fp16
__device__ __half g_win16[(size_t)NJ * DM];       // W_in in fp16
__device__ __half g_wcomb16[(size_t)DM * KCMB];   // combined out-proj weight, fp16
__device__ __half g_yg16[(size_t)NR * KCMB];      // gated scan output, fp16, ORIGINAL order

// ---------------- cross-scan permutations ------------------------------------
__device__ __forceinline__ int orig_of_scan(int d, int p) {
    int hi = p >> 5, lo = p & 31;
    if (d == 0) return p;
    if (d == 1) return hi * 32 + (31 - lo);
    if (d == 2) return lo * 32 + hi;
    return (31 - lo) * 32 + hi;
}
__device__ __forceinline__ int scan_of_orig(int d, int l) {
    int h = l >> 5, w = l & 31;
    if (d == 0) return l;
    if (d == 1) return h * 32 + (31 - w);
    if (d == 2) return w * 32 + h;
    return w * 32 + (31 - h);
}

// ---------------- mma / cp.async / ldmatrix helpers ---------------------------
__device__ __forceinline__ uint32_t to_tf32(float x) {
    uint32_t r;
    asm("cvt.rna.tf32.f32 %0, %1;" : "=r"(r) : "f"(x));
    return r;
}
__device__ __forceinline__ void mma_tf32(float* c, const uint32_t* a, const uint32_t* b) {
    asm volatile(
        "mma.sync.aligned.m16n8k8.row.col.f32.tf32.tf32.f32 "
        "{%0,%1,%2,%3}, {%4,%5,%6,%7}, {%8,%9}, {%0,%1,%2,%3};"
        : "+f"(c[0]), "+f"(c[1]), "+f"(c[2]), "+f"(c[3])
        : "r"(a[0]), "r"(a[1]), "r"(a[2]), "r"(a[3]), "r"(b[0]), "r"(b[1]));
}
__device__ __forceinline__ void mma_fp16(float* c, const uint32_t* a, const uint32_t* b) {
    asm volatile(
        "mma.sync.aligned.m16n8k16.row.col.f32.f16.f16.f32 "
        "{%0,%1,%2,%3}, {%4,%5,%6,%7}, {%8,%9}, {%0,%1,%2,%3};"
        : "+f"(c[0]), "+f"(c[1]), "+f"(c[2]), "+f"(c[3])
        : "r"(a[0]), "r"(a[1]), "r"(a[2]), "r"(a[3]), "r"(b[0]), "r"(b[1]));
}
__device__ __forceinline__ void ldsm4(uint32_t* r, uint32_t addr) {
    asm volatile("ldmatrix.sync.aligned.m8n8.x4.shared.b16 {%0,%1,%2,%3}, [%4];"
        : "=r"(r[0]), "=r"(r[1]), "=r"(r[2]), "=r"(r[3]) : "r"(addr));
}
__device__ __forceinline__ void cpa16cg(void* sm, const void* g) {
    uint32_t sa = (uint32_t)__cvta_generic_to_shared(sm);
    asm volatile("cp.async.cg.shared.global [%0], [%1], 16;" :: "r"(sa), "l"(g));
}
#define CP_COMMIT() asm volatile("cp.async.commit_group;")
#define CP_WAIT2() asm volatile("cp.async.wait_group 2;")

// ---------------- prep: fp32 -> fp16 ------------------------------------------
__global__ __launch_bounds__(256) void k_tohalf(const float4* __restrict__ src,
                                                __half2* __restrict__ dst, int n4) {
    int i = blockIdx.x * 256 + threadIdx.x;
    if (i < n4) {
        float4 v = src[i];
        dst[2 * i] = __floats2half2_rn(v.x, v.y);
        dst[2 * i + 1] = __floats2half2_rn(v.z, v.w);
    }
}

// ---------------- K_GEMM big (FP16 mma + ldmatrix, 256 thr, 128x128): inproj -
// Epilogue stores rows permuted to the direction's scan order.
__global__ __launch_bounds__(256, 2) void k_gemm_big(
    const __half* __restrict__ A, const __half* __restrict__ B,
    float* __restrict__ C, int K, int ldc) {
    __shared__ __align__(16) uint32_t As[4][128][12];
    __shared__ __align__(16) uint32_t Bs[4][128][12];
    const int tid = threadIdx.x;
    const int m0 = blockIdx.y * 128, n0 = blockIdx.x * 128;
    const int dd = blockIdx.x / 12;
    const int arow = tid & 127, au = (tid >> 7) * 4;
    const int lane = tid & 31, warp = tid >> 5;
    const int wm = warp >> 2, wn = warp & 3;
    const int g = lane >> 2, t = lane & 3;

    const __half* Ag = A + (size_t)(m0 + arow) * K + au * 2;
    const __half* Bg = B + (size_t)(n0 + arow) * K + au * 2;

    // ldmatrix per-lane address offsets (bytes within a stage)
    const uint32_t asBase = (uint32_t)__cvta_generic_to_shared(&As[0][0][0]);
    const uint32_t bsBase = (uint32_t)__cvta_generic_to_shared(&Bs[0][0][0]);
    const uint32_t aOff = (uint32_t)((wm * 64 + (lane & 15)) * 48 + ((lane >> 4) * 16));
    const uint32_t bOff = (uint32_t)((wn * 32 + ((lane >> 4) << 3) + (lane & 7)) * 48 +
                                     (((lane >> 3) & 1) * 16));

    float acc[4][4][4];
#pragma unroll
    for (int i = 0; i < 4; i++)
#pragma unroll
        for (int j = 0; j < 4; j++)
#pragma unroll
            for (int q = 0; q < 4; q++) acc[i][j][q] = 0.f;

    const int nt = K >> 4;
#pragma unroll
    for (int s = 0; s < 3; s++) {
        cpa16cg(&As[s][arow][au], Ag + s * 16);
        cpa16cg(&Bs[s][arow][au], Bg + s * 16);
        CP_COMMIT();
    }

    for (int tt = 0; tt < nt; tt++) {
        CP_WAIT2();
        __syncthreads();
        const int st = tt & 3;
        const uint32_t aS = asBase + st * 6144 + aOff;
        const uint32_t bS = bsBase + st * 6144 + bOff;
        uint32_t afr[4][4], bt0[4], bt1[4];
        ldsm4(afr[0], aS);
        ldsm4(afr[1], aS + 768);
        ldsm4(afr[2], aS + 1536);
        ldsm4(afr[3], aS + 2304);
        ldsm4(bt0, bS);
        ldsm4(bt1, bS + 768);
#pragma unroll
        for (int i = 0; i < 4; i++) {
            mma_fp16(acc[i][0], afr[i], &bt0[0]);
            mma_fp16(acc[i][1], afr[i], &bt0[2]);
            mma_fp16(acc[i][2], afr[i], &bt1[0]);
            mma_fp16(acc[i][3], afr[i], &bt1[2]);
        }
        const int tn = tt + 3;
        if (tn < nt) {
            cpa16cg(&As[tn & 3][arow][au], Ag + tn * 16);
            cpa16cg(&Bs[tn & 3][arow][au], Bg + tn * 16);
        }
        CP_COMMIT();
    }

#pragma unroll
    for (int i = 0; i < 4; i++) {
        const int r0 = m0 + wm * 64 + i * 16 + g;
        const int r1 = r0 + 8;
        const int p0r = (r0 & ~1023) + scan_of_orig(dd, r0 & 1023);
        const int p1r = (r1 & ~1023) + scan_of_orig(dd, r1 & 1023);
#pragma unroll
        for (int j = 0; j < 4; j++) {
            const int cidx = n0 + wn * 32 + j * 8 + 2 * t;
            *(float2*)(C + (size_t)p0r * ldc + cidx) = make_float2(acc[i][j][0], acc[i][j][1]);
            *(float2*)(C + (size_t)p1r * ldc + cidx) = make_float2(acc[i][j][2], acc[i][j][3]);
        }
    }
}

// ---------------- K_GEMM small (FP16 mma + ldmatrix, 128 thr, 128x64): outproj
__global__ __launch_bounds__(128, 4) void k_gemm_small(
    const __half* __restrict__ A, const __half* __restrict__ B,
    float* __restrict__ C, int K, int ldc,
    const float* __restrict__ X, const float* __restrict__ bias) {
    __shared__ __align__(16) uint32_t As[4][128][12];
    __shared__ __align__(16) uint32_t Bs[4][64][12];
    const int tid = threadIdx.x;
    const int m0 = blockIdx.y * 128, n0 = blockIdx.x * 64;
    const int lane = tid & 31, warp = tid >> 5;
    const int wm = warp >> 1, wn = warp & 1;
    const int g = lane >> 2, t = lane & 3;

    const __half* Ag = A + (size_t)(m0 + tid) * K;
    const __half* Bg = B + (size_t)(n0 + (tid & 63)) * K;
    const bool bldr = (tid < 64);

    const uint32_t asBase = (uint32_t)__cvta_generic_to_shared(&As[0][0][0]);
    const uint32_t bsBase = (uint32_t)__cvta_generic_to_shared(&Bs[0][0][0]);
    const uint32_t aOff = (uint32_t)((wm * 64 + (lane & 15)) * 48 + ((lane >> 4) * 16));
    const uint32_t bOff = (uint32_t)((wn * 32 + ((lane >> 4) << 3) + (lane & 7)) * 48 +
                                     (((lane >> 3) & 1) * 16));

    float acc[4][4][4];
#pragma unroll
    for (int i = 0; i < 4; i++)
#pragma unroll
        for (int j = 0; j < 4; j++)
#pragma unroll
            for (int q = 0; q < 4; q++) acc[i][j][q] = 0.f;

    const int nt = K >> 4;
#pragma unroll
    for (int s = 0; s < 3; s++) {
        cpa16cg(&As[s][tid][0], Ag + s * 16);
        cpa16cg(&As[s][tid][4], Ag + s * 16 + 8);
        if (bldr) {
            cpa16cg(&Bs[s][tid][0], Bg + s * 16);
            cpa16cg(&Bs[s][tid][4], Bg + s * 16 + 8);
        }
        CP_COMMIT();
    }

    for (int tt = 0; tt < nt; tt++) {
        CP_WAIT2();
        __syncthreads();
        const int st = tt & 3;
        const uint32_t aS = asBase + st * 6144 + aOff;
        const uint32_t bS = bsBase + st * 3072 + bOff;
        uint32_t afr[4][4], bt0[4], bt1[4];
        ldsm4(afr[0], aS);
        ldsm4(afr[1], aS + 768);
        ldsm4(afr[2], aS + 1536);
        ldsm4(afr[3], aS + 2304);
        ldsm4(bt0, bS);
        ldsm4(bt1, bS + 768);
#pragma unroll
        for (int i = 0; i < 4; i++) {
            mma_fp16(acc[i][0], afr[i], &bt0[0]);
            mma_fp16(acc[i][1], afr[i], &bt0[2]);
            mma_fp16(acc[i][2], afr[i], &bt1[0]);
            mma_fp16(acc[i][3], afr[i], &bt1[2]);
        }
        const int tn = tt + 3;
        if (tn < nt) {
            cpa16cg(&As[tn & 3][tid][0], Ag + tn * 16);
            cpa16cg(&As[tn & 3][tid][4], Ag + tn * 16 + 8);
            if (bldr) {
                cpa16cg(&Bs[tn & 3][tid][0], Bg + tn * 16);
                cpa16cg(&Bs[tn & 3][tid][4], Bg + tn * 16 + 8);
            }
        }
        CP_COMMIT();
    }

#pragma unroll
    for (int i = 0; i < 4; i++) {
        const int r0 = m0 + wm * 64 + i * 16 + g;
        const int r1 = r0 + 8;
#pragma unroll
        for (int j = 0; j < 4; j++) {
            const int cidx = n0 + wn * 32 + j * 8 + 2 * t;
            float2 s0 = make_float2(acc[i][j][0], acc[i][j][1]);
            float2 s1 = make_float2(acc[i][j][2], acc[i][j][3]);
            float2 x0 = *(const float2*)(X + (size_t)r0 * DM + cidx);
            float2 x1 = *(const float2*)(X + (size_t)r1 * DM + cidx);
            float2 bb = *(const float2*)(bias + cidx);
            s0.x += x0.x + bb.x; s0.y += x0.y + bb.y;
            s1.x += x1.x + bb.x; s1.y += x1.y + bb.y;
            *(float2*)(C + (size_t)r0 * ldc + cidx) = s0;
            *(float2*)(C + (size_t)r1 * ldc + cidx) = s1;
        }
    }
}

// ---------------- K3: x_dbl (TF32 mma): per d, [8192x768]@[56x768]^T ---------
__global__ __launch_bounds__(256) void k_xdbl_tf32(const float* __restrict__ Wx) {
    __shared__ __align__(16) uint32_t As[2][16][136];
    __shared__ __align__(16) uint32_t Bs[2][16][72];
    const int tid = threadIdx.x;
    const int d = blockIdx.y;
    const int m0 = blockIdx.x * 128;
    const float* Auc = g_uc + (size_t)d * NR * DI;
    const float* Bw = Wx + (size_t)d * NXD * DI;

    const int arow = tid & 127, ak = (tid >> 7) * 8;
    const int brow = tid & 63, bk = (tid >> 6) * 4;
    const int lane = tid & 31, warp = tid >> 5;
    const int wm = warp >> 1, wn = warp & 1;
    const int g = lane >> 2, kA = lane & 3;

    const float* Ag = Auc + (size_t)(m0 + arow) * DI + ak;
    const float* Bg = Bw + (size_t)brow * DI + bk;
    const bool bvalid = (brow < NXD);

    float acc[2][4][4];
#pragma unroll
    for (int i = 0; i < 2; i++)
#pragma unroll
        for (int j = 0; j < 4; j++)
#pragma unroll
            for (int q = 0; q < 4; q++) acc[i][j][q] = 0.f;

    const int ntiles = DI >> 4;
    float4 pa0, pa1, pb0;
    pa0 = *(const float4*)(Ag);
    pa1 = *(const float4*)(Ag + 4);
    pb0 = bvalid ? *(const float4*)(Bg) : make_float4(0.f, 0.f, 0.f, 0.f);
    {
        float av[8] = {pa0.x, pa0.y, pa0.z, pa0.w, pa1.x, pa1.y, pa1.z, pa1.w};
        float bv[4] = {pb0.x, pb0.y, pb0.z, pb0.w};
#pragma unroll
        for (int q = 0; q < 8; q++) As[0][ak + q][arow] = to_tf32(av[q]);
#pragma unroll
        for (int q = 0; q < 4; q++) Bs[0][bk + q][brow] = to_tf32(bv[q]);
    }
    __syncthreads();

    for (int t = 0; t < ntiles; t++) {
        const int cur = t & 1;
        if (t + 1 < ntiles) {
            const int k0 = (t + 1) << 4;
            pa0 = *(const float4*)(Ag + k0);
            pa1 = *(const float4*)(Ag + k0 + 4);
            pb0 = bvalid ? *(const float4*)(Bg + k0) : make_float4(0.f, 0.f, 0.f, 0.f);
        }
#pragma unroll
        for (int k8 = 0; k8 < 16; k8 += 8) {
            uint32_t afr[2][4], bfr[4][2];
            const int kr0 = k8 + kA, kr1 = k8 + kA + 4;
#pragma unroll
            for (int i = 0; i < 2; i++) {
                const int am = wm * 32 + i * 16 + g;
                afr[i][0] = As[cur][kr0][am];
                afr[i][1] = As[cur][kr0][am + 8];
                afr[i][2] = As[cur][kr1][am];
                afr[i][3] = As[cur][kr1][am + 8];
            }
#pragma unroll
            for (int j = 0; j < 4; j++) {
                const int bn = wn * 32 + j * 8 + g;
                bfr[j][0] = Bs[cur][kr0][bn];
                bfr[j][1] = Bs[cur][kr1][bn];
            }
#pragma unroll
            for (int i = 0; i < 2; i++)
#pragma unroll
                for (int j = 0; j < 4; j++) mma_tf32(acc[i][j], afr[i], bfr[j]);
        }
        if (t + 1 < ntiles) {
            const int nxt = cur ^ 1;
            float av[8] = {pa0.x, pa0.y, pa0.z, pa0.w, pa1.x, pa1.y, pa1.z, pa1.w};
            float bv[4] = {pb0.x, pb0.y, pb0.z, pb0.w};
#pragma unroll
            for (int q = 0; q < 8; q++) As[nxt][ak + q][arow] = to_tf32(av[q]);
#pragma unroll
            for (int q = 0; q < 4; q++) Bs[nxt][bk + q][brow] = to_tf32(bv[q]);
            __syncthreads();
        }
    }

#pragma unroll
    for (int i = 0; i < 2; i++) {
        const int r0 = m0 + wm * 32 + i * 16 + g;
        const int r1 = r0 + 8;
#pragma unroll
        for (int j = 0; j < 4; j++) {
            const int cidx = wn * 32 + j * 8 + 2 * kA;
            *(float2*)(g_xdbl + ((size_t)d * NR + r0) * NXDP + cidx) =
                make_float2(acc[i][j][0], acc[i][j][1]);
            *(float2*)(g_xdbl + ((size_t)d * NR + r1) * NXDP + cidx) =
                make_float2(acc[i][j][2], acc[i][j][3]);
        }
    }
}

// ---------------- K0: W_comb (fp16 output) ------------------------------------
__global__ __launch_bounds__(256) void k_wcomb(const float* __restrict__ Wproj,
                                               const float* __restrict__ Wout) {
    __shared__ float As[16 * 68];
    __shared__ float Bs[16 * 68];
    const int d = blockIdx.z;
    const int j0 = blockIdx.y * 64, c0 = blockIdx.x * 64;
    const int tid = threadIdx.x;
    const int tx = tid & 15, ty = tid >> 4;
    const int lm = tid >> 2, lk = (tid & 3) * 4;
    float acc[4][4];
#pragma unroll
    for (int i = 0; i < 4; i++)
#pragma unroll
        for (int j = 0; j < 4; j++) acc[i][j] = 0.f;

    for (int k0 = 0; k0 < DM; k0 += 16) {
        float4 av = *(const float4*)(Wproj + (size_t)(j0 + lm) * (4 * DM) + d * DM + k0 + lk);
        As[(lk + 0) * 68 + lm] = av.x;
        As[(lk + 1) * 68 + lm] = av.y;
        As[(lk + 2) * 68 + lm] = av.z;
        As[(lk + 3) * 68 + lm] = av.w;
#pragma unroll
        for (int pass = 0; pass < 4; pass++) {
            int idx = tid + pass * 256;
            int kk = idx >> 6, cc = idx & 63;
            Bs[kk * 68 + cc] = Wout[((size_t)d * DM + k0 + kk) * DI + c0 + cc];
        }
        __syncthreads();
#pragma unroll
        for (int kk = 0; kk < 16; kk++) {
            float4 a = *(const float4*)(As + kk * 68 + ty * 4);
            float4 b = *(const float4*)(Bs + kk * 68 + tx * 4);
            float am[4] = {a.x, a.y, a.z, a.w};
            float bm[4] = {b.x, b.y, b.z, b.w};
#pragma unroll
            for (int i = 0; i < 4; i++)
#pragma unroll
                for (int j = 0; j < 4; j++) acc[i][j] += am[i] * bm[j];
        }
        __syncthreads();
    }
#pragma unroll
    for (int i = 0; i < 4; i++) {
        __half2* dst = (__half2*)(g_wcomb16 + (size_t)(j0 + ty * 4 + i) * KCMB + d * DI + c0 + tx * 4);
        dst[0] = __floats2half2_rn(acc[i][0], acc[i][1]);
        dst[1] = __floats2half2_rn(acc[i][2], acc[i][3]);
    }
}

// ---------------- K2: depthwise causal conv (sequential scan rows) + SiLU ----
__global__ __launch_bounds__(128) void k_conv2(const float* __restrict__ convw,
                                               const float* __restrict__ convb) {
    const int tid = threadIdx.x;
    const int c = blockIdx.x * 128 + tid;
    const int seg = blockIdx.y;
    const int bz = blockIdx.z;
    const int d = bz >> 3, b = bz & 7;
    const int p0 = seg * 16;

    float4 w4 = *(const float4*)(convw + ((size_t)d * DI + c) * 4);
    const float bias = convb[d * DI + c];
    const float* xzbase = g_xz + (size_t)b * SEQ * NJ + d * DXZ + c;

    float v[19];
#pragma unroll
    for (int j = 0; j < 19; j++) {
        int q = p0 + j - 3;
        v[j] = (q >= 0) ? xzbase[(size_t)q * NJ] : 0.f;
    }
    float* ucp = g_uc + ((size_t)(d * 8 + b) * SEQ + p0) * DI + c;
#pragma unroll
    for (int k = 0; k < 16; k++) {
        float acc = bias + w4.x * v[k] + w4.y * v[k + 1] + w4.z * v[k + 2] + w4.w * v[k + 3];
        ucp[(size_t)k * DI] = __fdividef(acc, 1.f + __expf(-acc));
    }
}

// ---------------- K4a: scan pass1 — dq store + chunk summaries ---------------
__global__ __launch_bounds__(128) void k_scanP(const float* __restrict__ Alog,
                                               const float* __restrict__ Wdt,
                                               const float* __restrict__ bdt) {
    __shared__ __align__(16) float xs[2][8][NXDP];
    const int d = blockIdx.z;
    const int b = blockIdx.y >> 3, j = blockIdx.y & 7;
    const int tid = threadIdx.x;
    const int c = blockIdx.x * 128 + tid;
    const bool full = (j < 7);

    float w[24];
    {
        const float* wr = Wdt + ((size_t)d * DI + c) * 24;
#pragma unroll
        for (int q = 0; q < 6; q++) {
            float4 vv = *(const float4*)(wr + q * 4);
            w[q * 4] = vv.x; w[q * 4 + 1] = vv.y; w[q * 4 + 2] = vv.z; w[q * 4 + 3] = vv.w;
        }
    }
    const float bb = bdt[d * DI + c];
    float a[NSTATE];
#pragma unroll
    for (int n = 0; n < NSTATE; n++) a[n] = -__expf(Alog[((size_t)d * DI + c) * NSTATE + n]);
    bool structured = true;
#pragma unroll
    for (int n = 1; n < NSTATE; n++) {
        float e = (float)(n + 1) * a[0];
        if (fabsf(a[n] - e) > 1e-4f * fabsf(e) + 1e-12f) structured = false;
    }

    const int p0 = j * CHS;
    const size_t rbase = (size_t)d * NR + (size_t)b * SEQ + p0;
    const float* uptr = g_uc + rbase * DI + c;
    const float* xrowbase = g_xdbl + rbase * NXDP;
    float2* dqp = g_dq + rbase * DI + c;
    const int srow = tid >> 4, scol = (tid & 15) * 4;

    *(float4*)&xs[0][srow][scol] = *(const float4*)(xrowbase + (size_t)srow * NXDP + scol);
    float ucur[8], unxt[8];
#pragma unroll
    for (int k = 0; k < 8; k++) ucur[k] = uptr[(size_t)k * DI];
    __syncthreads();

    float h[NSTATE];
#pragma unroll
    for (int n = 0; n < NSTATE; n++) h[n] = 0.f;
    float S = 0.f;

    const int NCH = CHS / 8;
    for (int ch = 0; ch < NCH; ch++) {
        const int buf = ch & 1;
        const int pn = (ch + 1 < NCH) ? (ch + 1) * 8 : ch * 8;
        *(float4*)&xs[buf ^ 1][srow][scol] =
            *(const float4*)(xrowbase + (size_t)(pn + srow) * NXDP + scol);
#pragma unroll
        for (int k = 0; k < 8; k++) unxt[k] = uptr[(size_t)(pn + k) * DI];
        const int pl = ch * 8;
#pragma unroll
        for (int k = 0; k < 8; k++) {
            const float* row = &xs[buf][k][0];
            float s = bb;
#pragma unroll
            for (int q = 0; q < 6; q++) {
                float4 vv = *(const float4*)(row + q * 4);
                s += vv.x * w[q * 4] + vv.y * w[q * 4 + 1] + vv.z * w[q * 4 + 2] + vv.w * w[q * 4 + 3];
            }
            float es = __expf(s);
            float qv = __fdividef(1.f, 1.f + es);
            float delta = (s > 80.f) ? s : __logf(1.f + es);
            dqp[(size_t)(pl + k) * DI] = make_float2(delta, qv);
            if (full) {
                float dA[16];
                if (structured) {
                    float q2 = qv * qv, q4 = q2 * q2, q8 = q4 * q4;
                    dA[0] = qv;       dA[1] = q2;       dA[2] = q2 * qv;     dA[3] = q4;
                    dA[4] = q4 * qv;  dA[5] = q4 * q2;  dA[6] = q4 * dA[2];  dA[7] = q8;
                    dA[8] = q8 * qv;  dA[9] = q8 * q2;  dA[10] = q8 * dA[2]; dA[11] = q8 * q4;
                    dA[12] = q8 * dA[4]; dA[13] = q8 * dA[5]; dA[14] = q8 * dA[6]; dA[15] = q8 * q8;
                } else {
#pragma unroll
                    for (int n = 0; n < 16; n++) dA[n] = __expf(delta * a[n]);
                }
                float4 B0 = *(const float4*)(row + 24);
                float4 B1 = *(const float4*)(row + 28);
                float4 B2 = *(const float4*)(row + 32);
                float4 B3 = *(const float4*)(row + 36);
                float Bv[16] = {B0.x, B0.y, B0.z, B0.w, B1.x, B1.y, B1.z, B1.w,
                                B2.x, B2.y, B2.z, B2.w, B3.x, B3.y, B3.z, B3.w};
                const float du = delta * ucur[k];
                S += delta;
#pragma unroll
                for (int n = 0; n < 16; n++) h[n] = dA[n] * h[n] + du * Bv[n];
            }
        }
#pragma unroll
        for (int k = 0; k < 8; k++) ucur[k] = unxt[k];
        __syncthreads();
    }

    if (full) {
        float P[16];
        if (structured) {
            float qS = __expf(a[0] * S);
            float q2 = qS * qS, q4 = q2 * q2, q8 = q4 * q4;
            P[0] = qS;       P[1] = q2;       P[2] = q2 * qS;    P[3] = q4;
            P[4] = q4 * qS;  P[5] = q4 * q2;  P[6] = q4 * P[2];  P[7] = q8;
            P[8] = q8 * qS;  P[9] = q8 * q2;  P[10] = q8 * P[2]; P[11] = q8 * q4;
            P[12] = q8 * P[4]; P[13] = q8 * P[5]; P[14] = q8 * P[6]; P[15] = q8 * q8;
        } else {
#pragma unroll
            for (int n = 0; n < 16; n++) P[n] = __expf(a[n] * S);
        }
        const size_t obase = (((size_t)(d * 8 + b) * NCHUNK + j) * NSTATE) * DI + c;
#pragma unroll
        for (int n = 0; n < 16; n++) {
            g_chkP[obase + (size_t)n * DI] = P[n];
            g_chkH[obase + (size_t)n * DI] = h[n];
        }
    }
}

// ---------------- K4b: combine chunk states ----------------------------------
__global__ __launch_bounds__(256) void k_comb() {
    const int c = blockIdx.x * 256 + threadIdx.x;
    const int b = blockIdx.y, d = blockIdx.z;
    float h[NSTATE];
#pragma unroll
    for (int n = 0; n < NSTATE; n++) h[n] = 0.f;
    const size_t base = ((size_t)(d * 8 + b) * NCHUNK) * NSTATE * DI + c;
    for (int j = 0; j < NCHUNK; j++) {
        const size_t jb = base + (size_t)j * NSTATE * DI;
#pragma unroll
        for (int n = 0; n < NSTATE; n++) g_hin[jb + (size_t)n * DI] = h[n];
        if (j < NCHUNK - 1) {
#pragma unroll
            for (int n = 0; n < NSTATE; n++)
                h[n] = g_chkP[jb + (size_t)n * DI] * h[n] + g_chkH[jb + (size_t)n * DI];
        }
    }
}

// ---------------- K4c: scan pass2 — recurrence + output (fp16 yg store) ------
__global__ __launch_bounds__(128) void k_scan2(const float* __restrict__ Alog,
                                               const float* __restrict__ Dpar) {
    __shared__ __align__(16) float xs[2][8][32];   // B|C only
    const int d = blockIdx.z;
    const int b = blockIdx.y >> 3, j = blockIdx.y & 7;
    const int tid = threadIdx.x;
    const int c = blockIdx.x * 128 + tid;

    const float Dp = Dpar[d * DI + c];
    const size_t abase = ((size_t)d * DI + c) * NSTATE;
    float a0 = -__expf(Alog[abase]);
    bool structured = true;
#pragma unroll
    for (int n = 1; n < NSTATE; n++) {
        float an = -__expf(Alog[abase + n]);
        float e = (float)(n + 1) * a0;
        if (fabsf(an - e) > 1e-4f * fabsf(e) + 1e-12f) structured = false;
    }

    const int p0 = j * CHS;
    const size_t rbase = (size_t)d * NR + (size_t)b * SEQ + p0;
    const float* uptr = g_uc + rbase * DI + c;
    const float2* dqp = g_dq + rbase * DI + c;
    const float* zbase = g_xz + ((size_t)b * SEQ + p0) * NJ + d * DXZ + DI + c;
    __half* ybase = g_yg16 + (size_t)b * SEQ * KCMB + (size_t)d * DI + c;
    const float* xrowbase = g_xdbl + rbase * NXDP + 24;

    float h[NSTATE];
    {
        const size_t hbase = (((size_t)(d * 8 + b) * NCHUNK + j) * NSTATE) * DI + c;
#pragma unroll
        for (int n = 0; n < NSTATE; n++) h[n] = g_hin[hbase + (size_t)n * DI];
    }

    const int srow = tid >> 3, scol = (tid & 7) * 4;
    if (tid < 64)
        *(float4*)&xs[0][srow][scol] = *(const float4*)(xrowbase + (size_t)srow * NXDP + scol);
    float ucur[8], zcur[8];
    float2 dqcur[8];
    float unxt[8], znxt[8];
    float2 dqnxt[8];
#pragma unroll
    for (int k = 0; k < 8; k++) {
        ucur[k] = uptr[(size_t)k * DI];
        dqcur[k] = dqp[(size_t)k * DI];
        zcur[k] = zbase[(size_t)k * NJ];
    }
    __syncthreads();

    const int NCH = CHS / 8;
    for (int ch = 0; ch < NCH; ch++) {
        const int buf = ch & 1;
        const int pn = (ch + 1 < NCH) ? (ch + 1) * 8 : ch * 8;
        if (tid < 64)
            *(float4*)&xs[buf ^ 1][srow][scol] =
                *(const float4*)(xrowbase + (size_t)(pn + srow) * NXDP + scol);
#pragma unroll
        for (int k = 0; k < 8; k++) {
            unxt[k] = uptr[(size_t)(pn + k) * DI];
            dqnxt[k] = dqp[(size_t)(pn + k) * DI];
            znxt[k] = zbase[(size_t)(pn + k) * NJ];
        }
        const int pl = ch * 8;
#pragma unroll
        for (int k = 0; k < 8; k++) {
            const float* row = &xs[buf][k][0];
            const float delta = dqcur[k].x;
            const float qv = dqcur[k].y;
            float dA[16];
            if (structured) {
                float q2 = qv * qv, q4 = q2 * q2, q8 = q4 * q4;
                dA[0] = qv;       dA[1] = q2;       dA[2] = q2 * qv;     dA[3] = q4;
                dA[4] = q4 * qv;  dA[5] = q4 * q2;  dA[6] = q4 * dA[2];  dA[7] = q8;
                dA[8] = q8 * qv;  dA[9] = q8 * q2;  dA[10] = q8 * dA[2]; dA[11] = q8 * q4;
                dA[12] = q8 * dA[4]; dA[13] = q8 * dA[5]; dA[14] = q8 * dA[6]; dA[15] = q8 * q8;
            } else {
#pragma unroll
                for (int n = 0; n < 16; n++)
                    dA[n] = __expf(delta * (-__expf(Alog[abase + n])));
            }
            float4 B0 = *(const float4*)(row + 0);
            float4 B1 = *(const float4*)(row + 4);
            float4 B2 = *(const float4*)(row + 8);
            float4 B3 = *(const float4*)(row + 12);
            float4 C0 = *(const float4*)(row + 16);
            float4 C1 = *(const float4*)(row + 20);
            float4 C2 = *(const float4*)(row + 24);
            float4 C3 = *(const float4*)(row + 28);
            float Bv[16] = {B0.x, B0.y, B0.z, B0.w, B1.x, B1.y, B1.z, B1.w,
                            B2.x, B2.y, B2.z, B2.w, B3.x, B3.y, B3.z, B3.w};
            float Cv[16] = {C0.x, C0.y, C0.z, C0.w, C1.x, C1.y, C1.z, C1.w,
                            C2.x, C2.y, C2.z, C2.w, C3.x, C3.y, C3.z, C3.w};
            const float u = ucur[k];
            const float du = delta * u;
            float acc0 = 0.f, acc1 = 0.f, acc2 = 0.f, acc3 = 0.f;
#pragma unroll
            for (int n = 0; n < 16; n += 4) {
                h[n] = dA[n] * h[n] + du * Bv[n];                 acc0 += h[n] * Cv[n];
                h[n + 1] = dA[n + 1] * h[n + 1] + du * Bv[n + 1]; acc1 += h[n + 1] * Cv[n + 1];
                h[n + 2] = dA[n + 2] * h[n + 2] + du * Bv[n + 2]; acc2 += h[n + 2] * Cv[n + 2];
                h[n + 3] = dA[n + 3] * h[n + 3] + du * Bv[n + 3]; acc3 += h[n + 3] * Cv[n + 3];
            }
            float y = (acc0 + acc1) + (acc2 + acc3) + u * Dp;
            float z = zcur[k];
            float sg = __fdividef(z, 1.f + __expf(-z));
            ybase[(size_t)orig_of_scan(d, p0 + pl + k) * KCMB] = __float2half_rn(y * sg);
        }
#pragma unroll
        for (int k = 0; k < 8; k++) {
            ucur[k] = unxt[k]; zcur[k] = znxt[k]; dqcur[k] = dqnxt[k];
        }
        __syncthreads();
    }
}

// ---------------- K6: LayerNorm ----------------------------------------------
__global__ __launch_bounds__(128) void k_ln(const float* __restrict__ gam,
                                            const float* __restrict__ bet,
                                            float* __restrict__ out) {
    const int r = blockIdx.x;
    const int tid = threadIdx.x;
    __shared__ float s1[4], s2[4];
    const float* row = g_r + (size_t)r * DM;
    float v0 = row[tid], v1 = row[tid + 128], v2 = row[tid + 256];
    float a = v0 + v1 + v2;
    float b = v0 * v0 + v1 * v1 + v2 * v2;
#pragma unroll
    for (int off = 16; off; off >>= 1) {
        a += __shfl_down_sync(0xffffffffu, a, off);
        b += __shfl_down_sync(0xffffffffu, b, off);
    }
    if ((tid & 31) == 0) { s1[tid >> 5] = a; s2[tid >> 5] = b; }
    __syncthreads();
    float ssum = s1[0] + s1[1] + s1[2] + s1[3];
    float ssq = s2[0] + s2[1] + s2[2] + s2[3];
    float mu = ssum * (1.f / 384.f);
    float var = ssq * (1.f / 384.f) - mu * mu;
    float rstd = rsqrtf(var + 1e-5f);
    out[(size_t)r * DM + tid] = gam[tid] * (v0 - mu) * rstd + bet[tid];
    out[(size_t)r * DM + tid + 128] = gam[tid + 128] * (v1 - mu) * rstd + bet[tid + 128];
    out[(size_t)r * DM + tid + 256] = gam[tid + 256] * (v2 - mu) * rstd + bet[tid + 256];
}

// ---------------- launch ------------------------------------------------------
extern "C" void kernel_launch(void* const* d_in, const int* in_sizes, int n_in,
                              void* d_out, int out_size) {
    const float* x = (const float*)d_in[0];
    const float* Win = (const float*)d_in[1];
    const float* convw = (const float*)d_in[2];
    const float* convb = (const float*)d_in[3];
    const float* Wx = (const float*)d_in[4];
    const float* Wdt = (const float*)d_in[5];
    const float* bdt = (const float*)d_in[6];
    const float* Alog = (const float*)d_in[7];
    const float* Dpar = (const float*)d_in[8];
    const float* Wout = (const float*)d_in[9];
    const float* Wproj = (const float*)d_in[10];
    const float* bproj = (const float*)d_in[11];
    const float* lng = (const float*)d_in[12];
    const float* lnb = (const float*)d_in[13];
    float* out = (float*)d_out;

    static float* p_xz = nullptr;
    static float* p_r = nullptr;
    static __half* p_x16 = nullptr;
    static __half* p_win16 = nullptr;
    static __half* p_wc16 = nullptr;
    static __half* p_yg16 = nullptr;
    if (!p_xz) {
        cudaGetSymbolAddress((void**)&p_xz, g_xz);
        cudaGetSymbolAddress((void**)&p_r, g_r);
        cudaGetSymbolAddress((void**)&p_x16, g_x16);
        cudaGetSymbolAddress((void**)&p_win16, g_win16);
        cudaGetSymbolAddress((void**)&p_wc16, g_wcomb16);
        cudaGetSymbolAddress((void**)&p_yg16, g_yg16);
    }

    const int nx4 = NR * DM / 4;
    const int nw4 = NJ * DM / 4;
    k_tohalf<<<(nx4 + 255) / 256, 256>>>((const float4*)x, (__half2*)p_x16, nx4);
    k_tohalf<<<(nw4 + 255) / 256, 256>>>((const float4*)Win, (__half2*)p_win16, nw4);
    k_wcomb<<<dim3(DI / 64, DM / 64, ND), 256>>>(Wproj, Wout);
    k_gemm_big<<<dim3(NJ / 128, NR / 128), 256>>>(p_x16, p_win16, p_xz, DM, NJ);
    k_conv2<<<dim3(DI / 128, SEQ / 16, ND * NB), 128>>>(convw, convb);
    k_xdbl_tf32<<<dim3(NR / 128, ND), 256>>>(Wx);
    k_scanP<<<dim3(DI / 128, NB * 8, ND), 128>>>(Alog, Wdt, bdt);
    k_comb<<<dim3(DI / 256, NB, ND), 256>>>();
    k_scan2<<<dim3(DI / 128, NB * 8, ND), 128>>>(Alog, Dpar);
    k_gemm_small<<<dim3(DM / 64, NR / 128), 128>>>(p_yg16, p_wc16, p_r, KCMB, DM, x, bproj);
    k_ln<<<NR, 128>>>(lng, lnb, out);
}